// round 3
// baseline (speedup 1.0000x reference)
#include <cuda_runtime.h>
#include <cuda_bf16.h>

#define Bc   2
#define Sc   2048
#define DIMc 1024
#define NHc  16
#define HDc  64
#define TTOT (Bc*Sc)
#define CHUNK (TTOT*DIMc)          // 4,194,304 elements

// One big scratch arena (bf16), offsets in CHUNK units:
// 0 xh | 1 xl | 2 wh(4 mats) | 3 wl(4 mats) | 4 qh | 5 ql | 6 kh | 7 kl
// 8 vh | 9 vl | 10 ch | 11 cl
__device__ __nv_bfloat16 g_buf[12ull * CHUNK];

// ---------------------------------------------------------------------------
// helpers
// ---------------------------------------------------------------------------
__device__ __forceinline__ unsigned sptr(const void* p) {
    return (unsigned)__cvta_generic_to_shared(p);
}
__device__ __forceinline__ void ldsm4(unsigned a, unsigned* r) {
    asm volatile("ldmatrix.sync.aligned.m8n8.x4.shared.b16 {%0,%1,%2,%3},[%4];"
        : "=r"(r[0]), "=r"(r[1]), "=r"(r[2]), "=r"(r[3]) : "r"(a));
}
__device__ __forceinline__ void ldsm4t(unsigned a, unsigned* r) {
    asm volatile("ldmatrix.sync.aligned.m8n8.x4.trans.shared.b16 {%0,%1,%2,%3},[%4];"
        : "=r"(r[0]), "=r"(r[1]), "=r"(r[2]), "=r"(r[3]) : "r"(a));
}
__device__ __forceinline__ void mma_bf16(float* c, const unsigned* a, unsigned b0, unsigned b1) {
    asm volatile(
        "mma.sync.aligned.m16n8k16.row.col.f32.bf16.bf16.f32 "
        "{%0,%1,%2,%3},{%4,%5,%6,%7},{%8,%9},{%0,%1,%2,%3};"
        : "+f"(c[0]), "+f"(c[1]), "+f"(c[2]), "+f"(c[3])
        : "r"(a[0]), "r"(a[1]), "r"(a[2]), "r"(a[3]), "r"(b0), "r"(b1));
}
__device__ __forceinline__ unsigned bcat(__nv_bfloat16 a, __nv_bfloat16 b) {
    return (unsigned)__bfloat16_as_ushort(a) | ((unsigned)__bfloat16_as_ushort(b) << 16);
}
__device__ __forceinline__ void split1(float x, __nv_bfloat16& h, __nv_bfloat16& l) {
    h = __float2bfloat16(x);
    l = __float2bfloat16(x - __bfloat162float(h));
}

// ---------------------------------------------------------------------------
// split fp32 -> bf16 hi/lo (x and weight matrices, one-time)
// ---------------------------------------------------------------------------
__global__ void split_kernel(const float* __restrict__ src,
                             __nv_bfloat16* __restrict__ h,
                             __nv_bfloat16* __restrict__ l, int n4)
{
    int i = blockIdx.x * blockDim.x + threadIdx.x;
    if (i >= n4) return;
    float4 v = reinterpret_cast<const float4*>(src)[i];
    __nv_bfloat16 h0,h1,h2,h3,l0,l1,l2,l3;
    split1(v.x,h0,l0); split1(v.y,h1,l1); split1(v.z,h2,l2); split1(v.w,h3,l3);
    reinterpret_cast<uint2*>(h)[i] = make_uint2(bcat(h0,h1), bcat(h2,h3));
    reinterpret_cast<uint2*>(l)[i] = make_uint2(bcat(l0,l1), bcat(l2,l3));
}

// ---------------------------------------------------------------------------
// Projection GEMM, bf16 hi/lo operands from gmem, bf16x3 MMA.
// Out[m][n] = sum_k A[m][k]*W[n][k].  BM=BN=128, BK=32, 256 thr, occ 2.
// MODE 0: write fp32; MODE 1: split-write bf16 hi/lo; MODE 2: rope then split.
// ---------------------------------------------------------------------------
#define SP 40   // smem stride (bf16): 80B rows -> LDSM conflict-free, 16B aligned

template<int MODE>
__global__ __launch_bounds__(256, 2) void proj_mma(
    const __nv_bfloat16* __restrict__ Ah_g, const __nv_bfloat16* __restrict__ Al_g,
    const __nv_bfloat16* __restrict__ Wh_g, const __nv_bfloat16* __restrict__ Wl_g,
    float* __restrict__ OutF,
    __nv_bfloat16* __restrict__ Oh, __nv_bfloat16* __restrict__ Ol,
    const float* __restrict__ fc, const float* __restrict__ fs)
{
    __shared__ __nv_bfloat16 Ah[128*SP], Al[128*SP], Bh[128*SP], Bl[128*SP];

    const int tid = threadIdx.x;
    const int warp = tid >> 5, lane = tid & 31;
    const int g = lane >> 3, r7 = lane & 7;
    const int mBase = blockIdx.y * 128, nBase = blockIdx.x * 128;
    const int wm = (warp & 3) * 32, wn = (warp >> 2) * 64;

    float c[2][8][4];
    #pragma unroll
    for (int i = 0; i < 2; i++)
        #pragma unroll
        for (int j = 0; j < 8; j++)
            #pragma unroll
            for (int k = 0; k < 4; k++) c[i][j][k] = 0.f;

    for (int d0 = 0; d0 < DIMc; d0 += 32) {
        #pragma unroll
        for (int i = 0; i < 2; i++) {
            int ch = tid + 256 * i;
            int r = ch >> 2, c8 = (ch & 3) * 8;
            size_t ga = (size_t)(mBase + r) * DIMc + d0 + c8;
            size_t gw = (size_t)(nBase + r) * DIMc + d0 + c8;
            *(uint4*)&Ah[r*SP + c8] = *(const uint4*)&Ah_g[ga];
            *(uint4*)&Al[r*SP + c8] = *(const uint4*)&Al_g[ga];
            *(uint4*)&Bh[r*SP + c8] = *(const uint4*)&Wh_g[gw];
            *(uint4*)&Bl[r*SP + c8] = *(const uint4*)&Wl_g[gw];
        }
        __syncthreads();
        #pragma unroll
        for (int kk = 0; kk < 32; kk += 16) {
            unsigned ah[2][4], al[2][4];
            #pragma unroll
            for (int mt = 0; mt < 2; mt++) {
                int row = wm + mt*16 + (g & 1)*8 + r7;
                int col = kk + (g >> 1)*8;
                ldsm4(sptr(&Ah[row*SP + col]), ah[mt]);
                ldsm4(sptr(&Al[row*SP + col]), al[mt]);
            }
            #pragma unroll
            for (int np = 0; np < 4; np++) {
                int row = wn + np*16 + (g >> 1)*8 + r7;
                int col = kk + (g & 1)*8;
                unsigned bh[4], bl[4];
                ldsm4(sptr(&Bh[row*SP + col]), bh);
                ldsm4(sptr(&Bl[row*SP + col]), bl);
                #pragma unroll
                for (int mt = 0; mt < 2; mt++) {
                    mma_bf16(c[mt][np*2],   ah[mt], bh[0], bh[1]);
                    mma_bf16(c[mt][np*2],   al[mt], bh[0], bh[1]);
                    mma_bf16(c[mt][np*2],   ah[mt], bl[0], bl[1]);
                    mma_bf16(c[mt][np*2+1], ah[mt], bh[2], bh[3]);
                    mma_bf16(c[mt][np*2+1], al[mt], bh[2], bh[3]);
                    mma_bf16(c[mt][np*2+1], ah[mt], bl[2], bl[3]);
                }
            }
        }
        __syncthreads();
    }

    #pragma unroll
    for (int mt = 0; mt < 2; mt++) {
        int row = mBase + wm + mt*16 + (lane >> 2);
        #pragma unroll
        for (int nt = 0; nt < 8; nt++) {
            int col = nBase + wn + nt*8 + (lane & 3)*2;
            float v0 = c[mt][nt][0], v1 = c[mt][nt][1];   // row
            float v2 = c[mt][nt][2], v3 = c[mt][nt][3];   // row+8
            if (MODE == 2) {
                int i = (col & 63) >> 1;
                int s0 = row & (Sc-1), s1 = (row + 8) & (Sc-1);
                float c0 = fc[s0*32 + i], sn0 = fs[s0*32 + i];
                float c1 = fc[s1*32 + i], sn1 = fs[s1*32 + i];
                float a0 = v0, b0 = v1, a1 = v2, b1 = v3;
                v0 = a0*c0 - b0*sn0; v1 = a0*sn0 + b0*c0;
                v2 = a1*c1 - b1*sn1; v3 = a1*sn1 + b1*c1;
            }
            if (MODE == 0) {
                *(float2*)(OutF + (size_t)row * DIMc + col)     = make_float2(v0, v1);
                *(float2*)(OutF + (size_t)(row+8) * DIMc + col) = make_float2(v2, v3);
            } else {
                __nv_bfloat16 h0,l0,h1,l1,h2,l2,h3,l3;
                split1(v0,h0,l0); split1(v1,h1,l1); split1(v2,h2,l2); split1(v3,h3,l3);
                *(unsigned*)&Oh[(size_t)row * DIMc + col]     = bcat(h0,h1);
                *(unsigned*)&Ol[(size_t)row * DIMc + col]     = bcat(l0,l1);
                *(unsigned*)&Oh[(size_t)(row+8) * DIMc + col] = bcat(h2,h3);
                *(unsigned*)&Ol[(size_t)(row+8) * DIMc + col] = bcat(l2,l3);
            }
        }
    }
}

// ---------------------------------------------------------------------------
// Attention, two-pass, bf16 hi/lo operands, fused normalization.
// Pass 1: scores -> exp -> rowsum + PV (no weight write).
// Pass 2: recompute scores -> exp * inv -> write normalized weights.
// ---------------------------------------------------------------------------
#define SQa 72    // 144B rows
#define SEa 136   // 272B rows

__global__ __launch_bounds__(512, 1) void attn_mma(
    float* __restrict__ attn,
    const __nv_bfloat16* __restrict__ Qh_g, const __nv_bfloat16* __restrict__ Ql_g,
    const __nv_bfloat16* __restrict__ Kh_g, const __nv_bfloat16* __restrict__ Kl_g,
    const __nv_bfloat16* __restrict__ Vh_g, const __nv_bfloat16* __restrict__ Vl_g,
    __nv_bfloat16* __restrict__ Ch_g, __nv_bfloat16* __restrict__ Cl_g)
{
    extern __shared__ __align__(16) char smraw[];
    __nv_bfloat16* Qh = (__nv_bfloat16*)smraw;
    __nv_bfloat16* Ql = Qh + 128*SQa;
    __nv_bfloat16* Kh = Ql + 128*SQa;
    __nv_bfloat16* Kl = Kh + 128*SQa;
    __nv_bfloat16* Vh = Kl + 128*SQa;
    __nv_bfloat16* Vl = Vh + 128*SQa;
    __nv_bfloat16* Eh = Vl + 128*SQa;
    __nv_bfloat16* El = Eh + 128*SEa;
    float* rowsum = (float*)(El + 128*SEa);

    const int tid = threadIdx.x;
    const int warp = tid >> 5, lane = tid & 31;
    const int g = lane >> 3, r7 = lane & 7;
    const int qBase = blockIdx.x * 128;
    const int h = blockIdx.y, b = blockIdx.z;

    const size_t qOff = (size_t)(b * Sc + qBase) * DIMc + h * HDc;
    const size_t kvOff = (size_t)b * Sc * DIMc + h * HDc;
    float* arow = attn + ((size_t)(b * NHc + h) * Sc + qBase) * Sc;

    if (tid < 128) rowsum[tid] = 0.f;

    // Q tile (persists across both passes)
    #pragma unroll
    for (int i = 0; i < 2; i++) {
        int ch = tid + 512 * i;
        int r = ch >> 3, c8 = (ch & 7) * 8;
        *(uint4*)&Qh[r*SQa + c8] = *(const uint4*)&Qh_g[qOff + (size_t)r * DIMc + c8];
        *(uint4*)&Ql[r*SQa + c8] = *(const uint4*)&Ql_g[qOff + (size_t)r * DIMc + c8];
    }

    const int wm = (warp & 3) * 32;
    const int wq = warp >> 2;
    const int wn = wq * 32;   // score col group
    const int wd = wq * 16;   // ctx col group

    float ctx[2][2][4] = {};
    float rs[4] = {0.f, 0.f, 0.f, 0.f};

    // ---------------- pass 1 ----------------
    for (int kt = 0; kt < Sc; kt += 128) {
        __syncthreads();
        #pragma unroll
        for (int i = 0; i < 2; i++) {
            int ch = tid + 512 * i;
            int r = ch >> 3, c8 = (ch & 7) * 8;
            size_t gk = kvOff + (size_t)(kt + r) * DIMc + c8;
            *(uint4*)&Kh[r*SQa + c8] = *(const uint4*)&Kh_g[gk];
            *(uint4*)&Kl[r*SQa + c8] = *(const uint4*)&Kl_g[gk];
            *(uint4*)&Vh[r*SQa + c8] = *(const uint4*)&Vh_g[gk];
            *(uint4*)&Vl[r*SQa + c8] = *(const uint4*)&Vl_g[gk];
        }
        __syncthreads();

        float s[2][4][4] = {};
        #pragma unroll
        for (int kk = 0; kk < 64; kk += 16) {
            unsigned ah[2][4], al[2][4];
            #pragma unroll
            for (int mt = 0; mt < 2; mt++) {
                int row = wm + mt*16 + (g & 1)*8 + r7;
                int col = kk + (g >> 1)*8;
                ldsm4(sptr(Qh + row*SQa + col), ah[mt]);
                ldsm4(sptr(Ql + row*SQa + col), al[mt]);
            }
            #pragma unroll
            for (int np = 0; np < 2; np++) {
                int row = wn + np*16 + (g >> 1)*8 + r7;
                int col = kk + (g & 1)*8;
                unsigned bh[4], bl[4];
                ldsm4(sptr(Kh + row*SQa + col), bh);
                ldsm4(sptr(Kl + row*SQa + col), bl);
                #pragma unroll
                for (int mt = 0; mt < 2; mt++) {
                    mma_bf16(s[mt][np*2],   ah[mt], bh[0], bh[1]);
                    mma_bf16(s[mt][np*2],   al[mt], bh[0], bh[1]);
                    mma_bf16(s[mt][np*2],   ah[mt], bl[0], bl[1]);
                    mma_bf16(s[mt][np*2+1], ah[mt], bh[2], bh[3]);
                    mma_bf16(s[mt][np*2+1], al[mt], bh[2], bh[3]);
                    mma_bf16(s[mt][np*2+1], ah[mt], bl[2], bl[3]);
                }
            }
        }

        // exp -> rowsum partials + stage E (hi/lo)
        #pragma unroll
        for (int mt = 0; mt < 2; mt++) {
            int row0 = wm + mt*16 + (lane >> 2);
            #pragma unroll
            for (int nt = 0; nt < 4; nt++) {
                int col = wn + nt*8 + (lane & 3)*2;
                float e0 = __expf(s[mt][nt][0] * 0.125f);
                float e1 = __expf(s[mt][nt][1] * 0.125f);
                float e2 = __expf(s[mt][nt][2] * 0.125f);
                float e3 = __expf(s[mt][nt][3] * 0.125f);
                rs[mt*2+0] += e0 + e1;
                rs[mt*2+1] += e2 + e3;
                __nv_bfloat16 h0,l0,h1,l1,h2,l2,h3,l3;
                split1(e0,h0,l0); split1(e1,h1,l1); split1(e2,h2,l2); split1(e3,h3,l3);
                *(unsigned*)(Eh + row0*SEa + col)     = bcat(h0, h1);
                *(unsigned*)(Eh + (row0+8)*SEa + col) = bcat(h2, h3);
                *(unsigned*)(El + row0*SEa + col)     = bcat(l0, l1);
                *(unsigned*)(El + (row0+8)*SEa + col) = bcat(l2, l3);
            }
        }
        __syncthreads();

        // PV
        #pragma unroll
        for (int kk = 0; kk < 128; kk += 16) {
            unsigned ah[2][4], al[2][4];
            #pragma unroll
            for (int mt = 0; mt < 2; mt++) {
                int row = wm + mt*16 + (g & 1)*8 + r7;
                int col = kk + (g >> 1)*8;
                ldsm4(sptr(Eh + row*SEa + col), ah[mt]);
                ldsm4(sptr(El + row*SEa + col), al[mt]);
            }
            int vrow = kk + (g & 1)*8 + r7;
            int vcol = wd + (g >> 1)*8;
            unsigned bh[4], bl[4];
            ldsm4t(sptr(Vh + vrow*SQa + vcol), bh);
            ldsm4t(sptr(Vl + vrow*SQa + vcol), bl);
            #pragma unroll
            for (int mt = 0; mt < 2; mt++) {
                mma_bf16(ctx[mt][0], ah[mt], bh[0], bh[1]);
                mma_bf16(ctx[mt][0], al[mt], bh[0], bh[1]);
                mma_bf16(ctx[mt][0], ah[mt], bl[0], bl[1]);
                mma_bf16(ctx[mt][1], ah[mt], bh[2], bh[3]);
                mma_bf16(ctx[mt][1], al[mt], bh[2], bh[3]);
                mma_bf16(ctx[mt][1], ah[mt], bl[2], bl[3]);
            }
        }
    }

    // rowsum -> inv
    #pragma unroll
    for (int mt = 0; mt < 2; mt++) {
        int row0 = wm + mt*16 + (lane >> 2);
        atomicAdd(&rowsum[row0],     rs[mt*2+0]);
        atomicAdd(&rowsum[row0 + 8], rs[mt*2+1]);
    }
    __syncthreads();
    if (tid < 128) rowsum[tid] = 1.0f / rowsum[tid];
    __syncthreads();

    // ctx epilogue: normalize + split-write bf16 hi/lo
    #pragma unroll
    for (int mt = 0; mt < 2; mt++) {
        int row0 = wm + mt*16 + (lane >> 2);
        float iv0 = rowsum[row0], iv1 = rowsum[row0 + 8];
        #pragma unroll
        for (int nt = 0; nt < 2; nt++) {
            int col = wd + nt*8 + (lane & 3)*2;
            float v0 = ctx[mt][nt][0] * iv0, v1 = ctx[mt][nt][1] * iv0;
            float v2 = ctx[mt][nt][2] * iv1, v3 = ctx[mt][nt][3] * iv1;
            __nv_bfloat16 h0,l0,h1,l1,h2,l2,h3,l3;
            split1(v0,h0,l0); split1(v1,h1,l1); split1(v2,h2,l2); split1(v3,h3,l3);
            size_t o0 = qOff + (size_t)row0 * DIMc + col;
            size_t o1 = qOff + (size_t)(row0+8) * DIMc + col;
            *(unsigned*)&Ch_g[o0] = bcat(h0,h1);
            *(unsigned*)&Cl_g[o0] = bcat(l0,l1);
            *(unsigned*)&Ch_g[o1] = bcat(h2,h3);
            *(unsigned*)&Cl_g[o1] = bcat(l2,l3);
        }
    }

    // hoist inverse row sums for pass 2
    float invr[2][2];
    #pragma unroll
    for (int mt = 0; mt < 2; mt++) {
        invr[mt][0] = rowsum[wm + mt*16 + (lane >> 2)];
        invr[mt][1] = rowsum[wm + mt*16 + 8 + (lane >> 2)];
    }

    // ---------------- pass 2: recompute scores, write normalized ----------------
    for (int kt = 0; kt < Sc; kt += 128) {
        __syncthreads();
        #pragma unroll
        for (int i = 0; i < 2; i++) {
            int ch = tid + 512 * i;
            int r = ch >> 3, c8 = (ch & 7) * 8;
            size_t gk = kvOff + (size_t)(kt + r) * DIMc + c8;
            *(uint4*)&Kh[r*SQa + c8] = *(const uint4*)&Kh_g[gk];
            *(uint4*)&Kl[r*SQa + c8] = *(const uint4*)&Kl_g[gk];
        }
        __syncthreads();

        float s[2][4][4] = {};
        #pragma unroll
        for (int kk = 0; kk < 64; kk += 16) {
            unsigned ah[2][4], al[2][4];
            #pragma unroll
            for (int mt = 0; mt < 2; mt++) {
                int row = wm + mt*16 + (g & 1)*8 + r7;
                int col = kk + (g >> 1)*8;
                ldsm4(sptr(Qh + row*SQa + col), ah[mt]);
                ldsm4(sptr(Ql + row*SQa + col), al[mt]);
            }
            #pragma unroll
            for (int np = 0; np < 2; np++) {
                int row = wn + np*16 + (g >> 1)*8 + r7;
                int col = kk + (g & 1)*8;
                unsigned bh[4], bl[4];
                ldsm4(sptr(Kh + row*SQa + col), bh);
                ldsm4(sptr(Kl + row*SQa + col), bl);
                #pragma unroll
                for (int mt = 0; mt < 2; mt++) {
                    mma_bf16(s[mt][np*2],   ah[mt], bh[0], bh[1]);
                    mma_bf16(s[mt][np*2],   al[mt], bh[0], bh[1]);
                    mma_bf16(s[mt][np*2],   ah[mt], bl[0], bl[1]);
                    mma_bf16(s[mt][np*2+1], ah[mt], bh[2], bh[3]);
                    mma_bf16(s[mt][np*2+1], al[mt], bh[2], bh[3]);
                    mma_bf16(s[mt][np*2+1], ah[mt], bl[2], bl[3]);
                }
            }
        }

        #pragma unroll
        for (int mt = 0; mt < 2; mt++) {
            int row0 = wm + mt*16 + (lane >> 2);
            #pragma unroll
            for (int nt = 0; nt < 4; nt++) {
                int col = wn + nt*8 + (lane & 3)*2;
                float e0 = __expf(s[mt][nt][0] * 0.125f) * invr[mt][0];
                float e1 = __expf(s[mt][nt][1] * 0.125f) * invr[mt][0];
                float e2 = __expf(s[mt][nt][2] * 0.125f) * invr[mt][1];
                float e3 = __expf(s[mt][nt][3] * 0.125f) * invr[mt][1];
                *(float2*)(arow + (size_t)row0 * Sc + kt + col)     = make_float2(e0, e1);
                *(float2*)(arow + (size_t)(row0+8) * Sc + kt + col) = make_float2(e2, e3);
            }
        }
    }
}

// ---------------------------------------------------------------------------
// Launcher
// ---------------------------------------------------------------------------
extern "C" void kernel_launch(void* const* d_in, const int* in_sizes, int n_in,
                              void* d_out, int out_size)
{
    const float* x  = (const float*)d_in[0];
    const float* wq = (const float*)d_in[1];
    const float* wk = (const float*)d_in[2];
    const float* wv = (const float*)d_in[3];
    const float* wo = (const float*)d_in[4];
    const float* fc = (const float*)d_in[5];
    const float* fs = (const float*)d_in[6];

    float* out  = (float*)d_out;
    float* attn = out + (size_t)Bc * Sc * DIMc;

    __nv_bfloat16* buf;
    cudaGetSymbolAddress((void**)&buf, g_buf);
    const size_t WM = (size_t)DIMc * DIMc;      // 1M elems per weight matrix
    __nv_bfloat16* XH = buf;
    __nv_bfloat16* XL = buf + 1ull*CHUNK;
    __nv_bfloat16* WH = buf + 2ull*CHUNK;
    __nv_bfloat16* WL = buf + 3ull*CHUNK;
    __nv_bfloat16* QH = buf + 4ull*CHUNK;
    __nv_bfloat16* QL = buf + 5ull*CHUNK;
    __nv_bfloat16* KH = buf + 6ull*CHUNK;
    __nv_bfloat16* KL = buf + 7ull*CHUNK;
    __nv_bfloat16* VH = buf + 8ull*CHUNK;
    __nv_bfloat16* VL = buf + 9ull*CHUNK;
    __nv_bfloat16* CH = buf + 10ull*CHUNK;
    __nv_bfloat16* CL = buf + 11ull*CHUNK;

    const int attnSmem = (6*128*SQa + 2*128*SEa) * 2 + 128*4;   // 180,736 B
    cudaFuncSetAttribute(attn_mma, cudaFuncAttributeMaxDynamicSharedMemorySize, attnSmem);

    // one-time splits
    int n4x = CHUNK / 4;
    split_kernel<<<(n4x + 255) / 256, 256>>>(x, XH, XL, n4x);
    int n4w = (int)(WM / 4);
    split_kernel<<<(n4w + 255) / 256, 256>>>(wq, WH + 0*WM, WL + 0*WM, n4w);
    split_kernel<<<(n4w + 255) / 256, 256>>>(wk, WH + 1*WM, WL + 1*WM, n4w);
    split_kernel<<<(n4w + 255) / 256, 256>>>(wv, WH + 2*WM, WL + 2*WM, n4w);
    split_kernel<<<(n4w + 255) / 256, 256>>>(wo, WH + 3*WM, WL + 3*WM, n4w);

    dim3 pgrid(DIMc / 128, TTOT / 128);   // (8, 32)
    proj_mma<2><<<pgrid, 256>>>(XH, XL, WH + 0*WM, WL + 0*WM, nullptr, QH, QL, fc, fs);
    proj_mma<2><<<pgrid, 256>>>(XH, XL, WH + 1*WM, WL + 1*WM, nullptr, KH, KL, fc, fs);
    proj_mma<1><<<pgrid, 256>>>(XH, XL, WH + 2*WM, WL + 2*WM, nullptr, VH, VL, nullptr, nullptr);

    attn_mma<<<dim3(Sc/128, NHc, Bc), 512, attnSmem>>>(attn, QH, QL, KH, KL, VH, VL, CH, CL);

    proj_mma<0><<<pgrid, 256>>>(CH, CL, WH + 3*WM, WL + 3*WM, out, nullptr, nullptr, nullptr, nullptr);
}

// round 4
// speedup vs baseline: 1.1074x; 1.1074x over previous
#include <cuda_runtime.h>
#include <cuda_bf16.h>

#define Bc   2
#define Sc   2048
#define DIMc 1024
#define NHc  16
#define HDc  64
#define TTOT (Bc*Sc)
#define CHUNK (TTOT*DIMc)          // 4,194,304 elements

// Scratch arena (bf16): 0 xh | 1 xl | 2 wh(4) | 3 wl(4) | 4 qh | 5 ql | 6 kh
// 7 kl | 8 vh | 9 vl | 10 ch | 11 cl
__device__ __nv_bfloat16 g_buf[12ull * CHUNK];

// ---------------------------------------------------------------------------
// helpers
// ---------------------------------------------------------------------------
__device__ __forceinline__ unsigned sptr(const void* p) {
    return (unsigned)__cvta_generic_to_shared(p);
}
__device__ __forceinline__ void cpa16(unsigned d, const void* s) {
    asm volatile("cp.async.cg.shared.global [%0], [%1], 16;" :: "r"(d), "l"(s));
}
__device__ __forceinline__ void cp_commit() { asm volatile("cp.async.commit_group;"); }
__device__ __forceinline__ void cp_wait0()  { asm volatile("cp.async.wait_group 0;"); }
__device__ __forceinline__ void cp_wait1()  { asm volatile("cp.async.wait_group 1;"); }

__device__ __forceinline__ void ldsm4(unsigned a, unsigned* r) {
    asm volatile("ldmatrix.sync.aligned.m8n8.x4.shared.b16 {%0,%1,%2,%3},[%4];"
        : "=r"(r[0]), "=r"(r[1]), "=r"(r[2]), "=r"(r[3]) : "r"(a));
}
__device__ __forceinline__ void ldsm4t(unsigned a, unsigned* r) {
    asm volatile("ldmatrix.sync.aligned.m8n8.x4.trans.shared.b16 {%0,%1,%2,%3},[%4];"
        : "=r"(r[0]), "=r"(r[1]), "=r"(r[2]), "=r"(r[3]) : "r"(a));
}
__device__ __forceinline__ void mma_bf16(float* c, const unsigned* a, unsigned b0, unsigned b1) {
    asm volatile(
        "mma.sync.aligned.m16n8k16.row.col.f32.bf16.bf16.f32 "
        "{%0,%1,%2,%3},{%4,%5,%6,%7},{%8,%9},{%0,%1,%2,%3};"
        : "+f"(c[0]), "+f"(c[1]), "+f"(c[2]), "+f"(c[3])
        : "r"(a[0]), "r"(a[1]), "r"(a[2]), "r"(a[3]), "r"(b0), "r"(b1));
}
__device__ __forceinline__ unsigned bcat(__nv_bfloat16 a, __nv_bfloat16 b) {
    return (unsigned)__bfloat16_as_ushort(a) | ((unsigned)__bfloat16_as_ushort(b) << 16);
}
__device__ __forceinline__ void split1(float x, __nv_bfloat16& h, __nv_bfloat16& l) {
    h = __float2bfloat16(x);
    l = __float2bfloat16(x - __bfloat162float(h));
}

// ---------------------------------------------------------------------------
// Fused one-time split: x + 4 weight matrices -> bf16 hi/lo
// ---------------------------------------------------------------------------
__global__ void split_all(const float* __restrict__ x,
                          const float* __restrict__ wq, const float* __restrict__ wk,
                          const float* __restrict__ wv, const float* __restrict__ wo,
                          __nv_bfloat16* __restrict__ XH, __nv_bfloat16* __restrict__ XL,
                          __nv_bfloat16* __restrict__ WH, __nv_bfloat16* __restrict__ WL)
{
    int i = blockIdx.x * blockDim.x + threadIdx.x;
    const int NX = CHUNK / 4;                 // 1,048,576
    const int NW = (DIMc * DIMc) / 4;         // 262,144
    const float* src; __nv_bfloat16 *dh, *dl; int idx;
    if (i < NX) { src = x; dh = XH; dl = XL; idx = i; }
    else {
        int j = i - NX;
        if (j >= 4 * NW) return;
        int m = j >> 18; idx = j & (NW - 1);
        src = (m == 0) ? wq : (m == 1) ? wk : (m == 2) ? wv : wo;
        dh = WH + (size_t)m * DIMc * DIMc;
        dl = WL + (size_t)m * DIMc * DIMc;
    }
    float4 v = reinterpret_cast<const float4*>(src)[idx];
    __nv_bfloat16 h0,h1,h2,h3,l0,l1,l2,l3;
    split1(v.x,h0,l0); split1(v.y,h1,l1); split1(v.z,h2,l2); split1(v.w,h3,l3);
    reinterpret_cast<uint2*>(dh)[idx] = make_uint2(bcat(h0,h1), bcat(h2,h3));
    reinterpret_cast<uint2*>(dl)[idx] = make_uint2(bcat(l0,l1), bcat(l2,l3));
}

// ---------------------------------------------------------------------------
// Projection GEMM: cp.async 2-stage pipeline, bf16x3 MMA.
// Out[m][n] = sum_k A[m][k]*W[n][k]. BM=BN=128, BK=32, 256 thr.
// MODE 0: fp32 out; MODE 1: split bf16 out; MODE 2: rope+split out.
// ---------------------------------------------------------------------------
#define SP 40            // smem row stride (bf16): 80B
#define PBUF (128*SP)    // elems per matrix buffer

template<int MODE>
__global__ __launch_bounds__(256, 2) void proj_mma(
    const __nv_bfloat16* __restrict__ Ah_g, const __nv_bfloat16* __restrict__ Al_g,
    const __nv_bfloat16* __restrict__ Wh_g, const __nv_bfloat16* __restrict__ Wl_g,
    float* __restrict__ OutF,
    __nv_bfloat16* __restrict__ Oh, __nv_bfloat16* __restrict__ Ol,
    const float* __restrict__ fc, const float* __restrict__ fs)
{
    extern __shared__ __align__(16) __nv_bfloat16 ps[];   // 2 stages x 4 bufs x PBUF

    const int tid = threadIdx.x;
    const int warp = tid >> 5, lane = tid & 31;
    const int g = lane >> 3, r7 = lane & 7;
    const int mBase = blockIdx.y * 128, nBase = blockIdx.x * 128;
    const int wm = (warp & 3) * 32, wn = (warp >> 2) * 64;

    float c[2][8][4];
    #pragma unroll
    for (int i = 0; i < 2; i++)
        #pragma unroll
        for (int j = 0; j < 8; j++)
            #pragma unroll
            for (int k = 0; k < 4; k++) c[i][j][k] = 0.f;

    // stage load: 2 chunks per thread per matrix
    auto pload = [&](int s, int d0) {
        __nv_bfloat16* base = ps + s * 4 * PBUF;
        #pragma unroll
        for (int i = 0; i < 2; i++) {
            int ch = tid + 256 * i;
            int r = ch >> 2, c8 = (ch & 3) * 8;
            size_t ga = (size_t)(mBase + r) * DIMc + d0 + c8;
            size_t gw = (size_t)(nBase + r) * DIMc + d0 + c8;
            cpa16(sptr(&base[0*PBUF + r*SP + c8]), &Ah_g[ga]);
            cpa16(sptr(&base[1*PBUF + r*SP + c8]), &Al_g[ga]);
            cpa16(sptr(&base[2*PBUF + r*SP + c8]), &Wh_g[gw]);
            cpa16(sptr(&base[3*PBUF + r*SP + c8]), &Wl_g[gw]);
        }
    };

    pload(0, 0); cp_commit();

    for (int t = 0; t < DIMc / 32; t++) {
        int cur = t & 1;
        cp_wait0();
        __syncthreads();
        if (t + 1 < DIMc / 32) { pload(cur ^ 1, (t + 1) * 32); cp_commit(); }

        __nv_bfloat16* Ah = ps + cur * 4 * PBUF;
        __nv_bfloat16* Al = Ah + PBUF;
        __nv_bfloat16* Bh = Ah + 2 * PBUF;
        __nv_bfloat16* Bl = Ah + 3 * PBUF;

        #pragma unroll
        for (int kk = 0; kk < 32; kk += 16) {
            unsigned ah[2][4], al[2][4];
            #pragma unroll
            for (int mt = 0; mt < 2; mt++) {
                int row = wm + mt*16 + (g & 1)*8 + r7;
                int col = kk + (g >> 1)*8;
                ldsm4(sptr(&Ah[row*SP + col]), ah[mt]);
                ldsm4(sptr(&Al[row*SP + col]), al[mt]);
            }
            #pragma unroll
            for (int np = 0; np < 4; np++) {
                int row = wn + np*16 + (g >> 1)*8 + r7;
                int col = kk + (g & 1)*8;
                unsigned bh[4], bl[4];
                ldsm4(sptr(&Bh[row*SP + col]), bh);
                ldsm4(sptr(&Bl[row*SP + col]), bl);
                #pragma unroll
                for (int mt = 0; mt < 2; mt++) {
                    mma_bf16(c[mt][np*2],   ah[mt], bh[0], bh[1]);
                    mma_bf16(c[mt][np*2],   al[mt], bh[0], bh[1]);
                    mma_bf16(c[mt][np*2],   ah[mt], bl[0], bl[1]);
                    mma_bf16(c[mt][np*2+1], ah[mt], bh[2], bh[3]);
                    mma_bf16(c[mt][np*2+1], al[mt], bh[2], bh[3]);
                    mma_bf16(c[mt][np*2+1], ah[mt], bl[2], bl[3]);
                }
            }
        }
    }

    #pragma unroll
    for (int mt = 0; mt < 2; mt++) {
        int row = mBase + wm + mt*16 + (lane >> 2);
        #pragma unroll
        for (int nt = 0; nt < 8; nt++) {
            int col = nBase + wn + nt*8 + (lane & 3)*2;
            float v0 = c[mt][nt][0], v1 = c[mt][nt][1];
            float v2 = c[mt][nt][2], v3 = c[mt][nt][3];
            if (MODE == 2) {
                int i = (col & 63) >> 1;
                int s0 = row & (Sc-1), s1 = (row + 8) & (Sc-1);
                float c0 = fc[s0*32 + i], sn0 = fs[s0*32 + i];
                float c1 = fc[s1*32 + i], sn1 = fs[s1*32 + i];
                float a0 = v0, b0 = v1, a1 = v2, b1 = v3;
                v0 = a0*c0 - b0*sn0; v1 = a0*sn0 + b0*c0;
                v2 = a1*c1 - b1*sn1; v3 = a1*sn1 + b1*c1;
            }
            if (MODE == 0) {
                *(float2*)(OutF + (size_t)row * DIMc + col)     = make_float2(v0, v1);
                *(float2*)(OutF + (size_t)(row+8) * DIMc + col) = make_float2(v2, v3);
            } else {
                __nv_bfloat16 h0,l0,h1,l1,h2,l2,h3,l3;
                split1(v0,h0,l0); split1(v1,h1,l1); split1(v2,h2,l2); split1(v3,h3,l3);
                *(unsigned*)&Oh[(size_t)row * DIMc + col]     = bcat(h0,h1);
                *(unsigned*)&Ol[(size_t)row * DIMc + col]     = bcat(l0,l1);
                *(unsigned*)&Oh[(size_t)(row+8) * DIMc + col] = bcat(h2,h3);
                *(unsigned*)&Ol[(size_t)(row+8) * DIMc + col] = bcat(l2,l3);
            }
        }
    }
}

// ---------------------------------------------------------------------------
// Attention: two-pass, cp.async pipelined (K double-buffered, V overlapped).
// Pass 1: scores->exp->rowsum+PV. Pass 2: recompute scores, write normalized.
// ---------------------------------------------------------------------------
#define SQa 72
#define SEa 136
#define QB (128*SQa)   // 9216 elems
#define EB (128*SEa)   // 17408 elems

__global__ __launch_bounds__(512, 1) void attn_mma(
    float* __restrict__ attn,
    const __nv_bfloat16* __restrict__ Qh_g, const __nv_bfloat16* __restrict__ Ql_g,
    const __nv_bfloat16* __restrict__ Kh_g, const __nv_bfloat16* __restrict__ Kl_g,
    const __nv_bfloat16* __restrict__ Vh_g, const __nv_bfloat16* __restrict__ Vl_g,
    __nv_bfloat16* __restrict__ Ch_g, __nv_bfloat16* __restrict__ Cl_g)
{
    extern __shared__ __align__(16) __nv_bfloat16 sm[];
    __nv_bfloat16* Qh = sm;                 // QB
    __nv_bfloat16* Ql = Qh + QB;
    __nv_bfloat16* Kst = Ql + QB;           // 2 stages x (h,l) x QB
    __nv_bfloat16* Vh = Kst + 4*QB;
    __nv_bfloat16* Vl = Vh + QB;
    __nv_bfloat16* Eh = Vl + QB;            // EB
    __nv_bfloat16* El = Eh + EB;
    float* rowsum = (float*)(El + EB);

    const int tid = threadIdx.x;
    const int warp = tid >> 5, lane = tid & 31;
    const int g = lane >> 3, r7 = lane & 7;
    const int qBase = blockIdx.x * 128;
    const int h = blockIdx.y, b = blockIdx.z;

    const size_t qOff = (size_t)(b * Sc + qBase) * DIMc + h * HDc;
    const size_t kvOff = (size_t)b * Sc * DIMc + h * HDc;
    float* arow = attn + ((size_t)(b * NHc + h) * Sc + qBase) * Sc;

    if (tid < 128) rowsum[tid] = 0.f;

    auto kload = [&](int s, int kt) {
        __nv_bfloat16* KH = Kst + s * 2 * QB;
        __nv_bfloat16* KL = KH + QB;
        #pragma unroll
        for (int i = 0; i < 2; i++) {
            int ch = tid + 512 * i;
            int r = ch >> 3, c8 = (ch & 7) * 8;
            size_t gk = kvOff + (size_t)(kt + r) * DIMc + c8;
            cpa16(sptr(&KH[r*SQa + c8]), &Kh_g[gk]);
            cpa16(sptr(&KL[r*SQa + c8]), &Kl_g[gk]);
        }
    };
    auto vload = [&](int kt) {
        #pragma unroll
        for (int i = 0; i < 2; i++) {
            int ch = tid + 512 * i;
            int r = ch >> 3, c8 = (ch & 7) * 8;
            size_t gk = kvOff + (size_t)(kt + r) * DIMc + c8;
            cpa16(sptr(&Vh[r*SQa + c8]), &Vh_g[gk]);
            cpa16(sptr(&Vl[r*SQa + c8]), &Vl_g[gk]);
        }
    };

    // prologue: Q + K_0 in one group
    #pragma unroll
    for (int i = 0; i < 2; i++) {
        int ch = tid + 512 * i;
        int r = ch >> 3, c8 = (ch & 7) * 8;
        size_t gq = qOff + (size_t)r * DIMc + c8;
        cpa16(sptr(&Qh[r*SQa + c8]), &Qh_g[gq]);
        cpa16(sptr(&Ql[r*SQa + c8]), &Ql_g[gq]);
    }
    kload(0, 0);
    cp_commit();

    const int wm = (warp & 3) * 32;
    const int wq = warp >> 2;
    const int wn = wq * 32;
    const int wd = wq * 16;

    float ctx[2][2][4] = {};
    float rs[4] = {0.f, 0.f, 0.f, 0.f};

    // ---------------- pass 1 ----------------
    for (int t = 0; t < Sc / 128; t++) {
        const int cur = t & 1;
        const int kt = t * 128;
        cp_wait0();
        __syncthreads();                     // K_t (and Q) visible; prev PV done
        vload(kt); cp_commit();              // group: V_t
        const bool pre = (t + 1 < Sc / 128);
        if (pre) { kload(cur ^ 1, kt + 128); cp_commit(); }   // group: K_{t+1}

        __nv_bfloat16* KH = Kst + cur * 2 * QB;
        __nv_bfloat16* KL = KH + QB;

        float s[2][4][4] = {};
        #pragma unroll
        for (int kk = 0; kk < 64; kk += 16) {
            unsigned ah[2][4], al[2][4];
            #pragma unroll
            for (int mt = 0; mt < 2; mt++) {
                int row = wm + mt*16 + (g & 1)*8 + r7;
                int col = kk + (g >> 1)*8;
                ldsm4(sptr(Qh + row*SQa + col), ah[mt]);
                ldsm4(sptr(Ql + row*SQa + col), al[mt]);
            }
            #pragma unroll
            for (int np = 0; np < 2; np++) {
                int row = wn + np*16 + (g >> 1)*8 + r7;
                int col = kk + (g & 1)*8;
                unsigned bh[4], bl[4];
                ldsm4(sptr(KH + row*SQa + col), bh);
                ldsm4(sptr(KL + row*SQa + col), bl);
                #pragma unroll
                for (int mt = 0; mt < 2; mt++) {
                    mma_bf16(s[mt][np*2],   ah[mt], bh[0], bh[1]);
                    mma_bf16(s[mt][np*2],   al[mt], bh[0], bh[1]);
                    mma_bf16(s[mt][np*2],   ah[mt], bl[0], bl[1]);
                    mma_bf16(s[mt][np*2+1], ah[mt], bh[2], bh[3]);
                    mma_bf16(s[mt][np*2+1], al[mt], bh[2], bh[3]);
                    mma_bf16(s[mt][np*2+1], ah[mt], bl[2], bl[3]);
                }
            }
        }

        if (pre) cp_wait1(); else cp_wait0();   // V_t arrived
        __syncthreads();                        // V visible; E free (prev PV done at top sync)

        #pragma unroll
        for (int mt = 0; mt < 2; mt++) {
            int row0 = wm + mt*16 + (lane >> 2);
            #pragma unroll
            for (int nt = 0; nt < 4; nt++) {
                int col = wn + nt*8 + (lane & 3)*2;
                float e0 = __expf(s[mt][nt][0] * 0.125f);
                float e1 = __expf(s[mt][nt][1] * 0.125f);
                float e2 = __expf(s[mt][nt][2] * 0.125f);
                float e3 = __expf(s[mt][nt][3] * 0.125f);
                rs[mt*2+0] += e0 + e1;
                rs[mt*2+1] += e2 + e3;
                __nv_bfloat16 h0,l0,h1,l1,h2,l2,h3,l3;
                split1(e0,h0,l0); split1(e1,h1,l1); split1(e2,h2,l2); split1(e3,h3,l3);
                *(unsigned*)(Eh + row0*SEa + col)     = bcat(h0, h1);
                *(unsigned*)(Eh + (row0+8)*SEa + col) = bcat(h2, h3);
                *(unsigned*)(El + row0*SEa + col)     = bcat(l0, l1);
                *(unsigned*)(El + (row0+8)*SEa + col) = bcat(l2, l3);
            }
        }
        __syncthreads();   // E visible

        #pragma unroll
        for (int kk = 0; kk < 128; kk += 16) {
            unsigned ah[2][4], al[2][4];
            #pragma unroll
            for (int mt = 0; mt < 2; mt++) {
                int row = wm + mt*16 + (g & 1)*8 + r7;
                int col = kk + (g >> 1)*8;
                ldsm4(sptr(Eh + row*SEa + col), ah[mt]);
                ldsm4(sptr(El + row*SEa + col), al[mt]);
            }
            int vrow = kk + (g & 1)*8 + r7;
            int vcol = wd + (g >> 1)*8;
            unsigned bh[4], bl[4];
            ldsm4t(sptr(Vh + vrow*SQa + vcol), bh);
            ldsm4t(sptr(Vl + vrow*SQa + vcol), bl);
            #pragma unroll
            for (int mt = 0; mt < 2; mt++) {
                mma_bf16(ctx[mt][0], ah[mt], bh[0], bh[1]);
                mma_bf16(ctx[mt][0], al[mt], bh[0], bh[1]);
                mma_bf16(ctx[mt][0], ah[mt], bl[0], bl[1]);
                mma_bf16(ctx[mt][1], ah[mt], bh[2], bh[3]);
                mma_bf16(ctx[mt][1], al[mt], bh[2], bh[3]);
                mma_bf16(ctx[mt][1], ah[mt], bl[2], bl[3]);
            }
        }
    }

    // rowsum -> inverse
    #pragma unroll
    for (int mt = 0; mt < 2; mt++) {
        int row0 = wm + mt*16 + (lane >> 2);
        atomicAdd(&rowsum[row0],     rs[mt*2+0]);
        atomicAdd(&rowsum[row0 + 8], rs[mt*2+1]);
    }
    __syncthreads();
    if (tid < 128) rowsum[tid] = 1.0f / rowsum[tid];
    __syncthreads();

    // ctx epilogue: normalize + split-write bf16
    #pragma unroll
    for (int mt = 0; mt < 2; mt++) {
        int row0 = wm + mt*16 + (lane >> 2);
        float iv0 = rowsum[row0], iv1 = rowsum[row0 + 8];
        #pragma unroll
        for (int nt = 0; nt < 2; nt++) {
            int col = wd + nt*8 + (lane & 3)*2;
            float v0 = ctx[mt][nt][0] * iv0, v1 = ctx[mt][nt][1] * iv0;
            float v2 = ctx[mt][nt][2] * iv1, v3 = ctx[mt][nt][3] * iv1;
            __nv_bfloat16 h0,l0,h1,l1,h2,l2,h3,l3;
            split1(v0,h0,l0); split1(v1,h1,l1); split1(v2,h2,l2); split1(v3,h3,l3);
            size_t o0 = qOff + (size_t)row0 * DIMc + col;
            size_t o1 = qOff + (size_t)(row0+8) * DIMc + col;
            *(unsigned*)&Ch_g[o0] = bcat(h0,h1);
            *(unsigned*)&Cl_g[o0] = bcat(l0,l1);
            *(unsigned*)&Ch_g[o1] = bcat(h2,h3);
            *(unsigned*)&Cl_g[o1] = bcat(l2,l3);
        }
    }

    float invr[2][2];
    #pragma unroll
    for (int mt = 0; mt < 2; mt++) {
        invr[mt][0] = rowsum[wm + mt*16 + (lane >> 2)];
        invr[mt][1] = rowsum[wm + mt*16 + 8 + (lane >> 2)];
    }
    __syncthreads();   // everyone past pass-1 buffers

    // ---------------- pass 2 ----------------
    kload(0, 0); cp_commit();
    for (int t = 0; t < Sc / 128; t++) {
        const int cur = t & 1;
        const int kt = t * 128;
        cp_wait0();
        __syncthreads();
        if (t + 1 < Sc / 128) { kload(cur ^ 1, kt + 128); cp_commit(); }

        __nv_bfloat16* KH = Kst + cur * 2 * QB;
        __nv_bfloat16* KL = KH + QB;

        float s[2][4][4] = {};
        #pragma unroll
        for (int kk = 0; kk < 64; kk += 16) {
            unsigned ah[2][4], al[2][4];
            #pragma unroll
            for (int mt = 0; mt < 2; mt++) {
                int row = wm + mt*16 + (g & 1)*8 + r7;
                int col = kk + (g >> 1)*8;
                ldsm4(sptr(Qh + row*SQa + col), ah[mt]);
                ldsm4(sptr(Ql + row*SQa + col), al[mt]);
            }
            #pragma unroll
            for (int np = 0; np < 2; np++) {
                int row = wn + np*16 + (g >> 1)*8 + r7;
                int col = kk + (g & 1)*8;
                unsigned bh[4], bl[4];
                ldsm4(sptr(KH + row*SQa + col), bh);
                ldsm4(sptr(KL + row*SQa + col), bl);
                #pragma unroll
                for (int mt = 0; mt < 2; mt++) {
                    mma_bf16(s[mt][np*2],   ah[mt], bh[0], bh[1]);
                    mma_bf16(s[mt][np*2],   al[mt], bh[0], bh[1]);
                    mma_bf16(s[mt][np*2],   ah[mt], bl[0], bl[1]);
                    mma_bf16(s[mt][np*2+1], ah[mt], bh[2], bh[3]);
                    mma_bf16(s[mt][np*2+1], al[mt], bh[2], bh[3]);
                    mma_bf16(s[mt][np*2+1], ah[mt], bl[2], bl[3]);
                }
            }
        }

        #pragma unroll
        for (int mt = 0; mt < 2; mt++) {
            int row0 = wm + mt*16 + (lane >> 2);
            #pragma unroll
            for (int nt = 0; nt < 4; nt++) {
                int col = wn + nt*8 + (lane & 3)*2;
                float e0 = __expf(s[mt][nt][0] * 0.125f) * invr[mt][0];
                float e1 = __expf(s[mt][nt][1] * 0.125f) * invr[mt][0];
                float e2 = __expf(s[mt][nt][2] * 0.125f) * invr[mt][1];
                float e3 = __expf(s[mt][nt][3] * 0.125f) * invr[mt][1];
                *(float2*)(arow + (size_t)row0 * Sc + kt + col)     = make_float2(e0, e1);
                *(float2*)(arow + (size_t)(row0+8) * Sc + kt + col) = make_float2(e2, e3);
            }
        }
    }
}

// ---------------------------------------------------------------------------
// Launcher
// ---------------------------------------------------------------------------
extern "C" void kernel_launch(void* const* d_in, const int* in_sizes, int n_in,
                              void* d_out, int out_size)
{
    const float* x  = (const float*)d_in[0];
    const float* wq = (const float*)d_in[1];
    const float* wk = (const float*)d_in[2];
    const float* wv = (const float*)d_in[3];
    const float* wo = (const float*)d_in[4];
    const float* fc = (const float*)d_in[5];
    const float* fs = (const float*)d_in[6];

    float* out  = (float*)d_out;
    float* attn = out + (size_t)Bc * Sc * DIMc;

    __nv_bfloat16* buf;
    cudaGetSymbolAddress((void**)&buf, g_buf);
    const size_t WM = (size_t)DIMc * DIMc;
    __nv_bfloat16* XH = buf;
    __nv_bfloat16* XL = buf + 1ull*CHUNK;
    __nv_bfloat16* WH = buf + 2ull*CHUNK;
    __nv_bfloat16* WL = buf + 3ull*CHUNK;
    __nv_bfloat16* QH = buf + 4ull*CHUNK;
    __nv_bfloat16* QL = buf + 5ull*CHUNK;
    __nv_bfloat16* KH = buf + 6ull*CHUNK;
    __nv_bfloat16* KL = buf + 7ull*CHUNK;
    __nv_bfloat16* VH = buf + 8ull*CHUNK;
    __nv_bfloat16* VL = buf + 9ull*CHUNK;
    __nv_bfloat16* CH = buf + 10ull*CHUNK;
    __nv_bfloat16* CL = buf + 11ull*CHUNK;

    const int projSmem = 2 * 4 * PBUF * 2;                       // 81,920 B
    cudaFuncSetAttribute(proj_mma<0>, cudaFuncAttributeMaxDynamicSharedMemorySize, projSmem);
    cudaFuncSetAttribute(proj_mma<1>, cudaFuncAttributeMaxDynamicSharedMemorySize, projSmem);
    cudaFuncSetAttribute(proj_mma<2>, cudaFuncAttributeMaxDynamicSharedMemorySize, projSmem);
    const int attnSmem = (8 * QB + 2 * EB) * 2 + 128 * 4;        // 217,600 B
    cudaFuncSetAttribute(attn_mma, cudaFuncAttributeMaxDynamicSharedMemorySize, attnSmem);

    int nSplit = CHUNK / 4 + DIMc * DIMc;   // 1M + 1M float4s
    split_all<<<(nSplit + 255) / 256, 256>>>(x, wq, wk, wv, wo, XH, XL, WH, WL);

    dim3 pgrid(DIMc / 128, TTOT / 128);
    proj_mma<2><<<pgrid, 256, projSmem>>>(XH, XL, WH + 0*WM, WL + 0*WM, nullptr, QH, QL, fc, fs);
    proj_mma<2><<<pgrid, 256, projSmem>>>(XH, XL, WH + 1*WM, WL + 1*WM, nullptr, KH, KL, fc, fs);
    proj_mma<1><<<pgrid, 256, projSmem>>>(XH, XL, WH + 2*WM, WL + 2*WM, nullptr, VH, VL, nullptr, nullptr);

    attn_mma<<<dim3(Sc/128, NHc, Bc), 512, attnSmem>>>(attn, QH, QL, KH, KL, VH, VL, CH, CL);

    proj_mma<0><<<pgrid, 256, projSmem>>>(CH, CL, WH + 3*WM, WL + 3*WM, out, nullptr, nullptr, nullptr, nullptr);
}

// round 5
// speedup vs baseline: 1.1450x; 1.0339x over previous
#include <cuda_runtime.h>
#include <cuda_bf16.h>

#define Bc   2
#define Sc   2048
#define DIMc 1024
#define NHc  16
#define HDc  64
#define TTOT (Bc*Sc)
#define CHUNK (TTOT*DIMc)          // 4,194,304 elements

// Scratch arena (bf16): 0 xh | 1 xl | 2 wh(4) | 3 wl(4) | 4 qh | 5 ql | 6 kh
// 7 kl | 8 vh | 9 vl | 10 ch | 11 cl
__device__ __nv_bfloat16 g_buf[12ull * CHUNK];

// ---------------------------------------------------------------------------
// helpers
// ---------------------------------------------------------------------------
__device__ __forceinline__ unsigned sptr(const void* p) {
    return (unsigned)__cvta_generic_to_shared(p);
}
__device__ __forceinline__ void cpa16(unsigned d, const void* s) {
    asm volatile("cp.async.cg.shared.global [%0], [%1], 16;" :: "r"(d), "l"(s));
}
__device__ __forceinline__ void cp_commit() { asm volatile("cp.async.commit_group;"); }
__device__ __forceinline__ void cp_wait0()  { asm volatile("cp.async.wait_group 0;"); }
__device__ __forceinline__ void cp_wait1()  { asm volatile("cp.async.wait_group 1;"); }

__device__ __forceinline__ void ldsm4(unsigned a, unsigned* r) {
    asm volatile("ldmatrix.sync.aligned.m8n8.x4.shared.b16 {%0,%1,%2,%3},[%4];"
        : "=r"(r[0]), "=r"(r[1]), "=r"(r[2]), "=r"(r[3]) : "r"(a));
}
__device__ __forceinline__ void ldsm4t(unsigned a, unsigned* r) {
    asm volatile("ldmatrix.sync.aligned.m8n8.x4.trans.shared.b16 {%0,%1,%2,%3},[%4];"
        : "=r"(r[0]), "=r"(r[1]), "=r"(r[2]), "=r"(r[3]) : "r"(a));
}
__device__ __forceinline__ void mma_bf16(float* c, const unsigned* a, unsigned b0, unsigned b1) {
    asm volatile(
        "mma.sync.aligned.m16n8k16.row.col.f32.bf16.bf16.f32 "
        "{%0,%1,%2,%3},{%4,%5,%6,%7},{%8,%9},{%0,%1,%2,%3};"
        : "+f"(c[0]), "+f"(c[1]), "+f"(c[2]), "+f"(c[3])
        : "r"(a[0]), "r"(a[1]), "r"(a[2]), "r"(a[3]), "r"(b0), "r"(b1));
}
__device__ __forceinline__ unsigned bcat(__nv_bfloat16 a, __nv_bfloat16 b) {
    return (unsigned)__bfloat16_as_ushort(a) | ((unsigned)__bfloat16_as_ushort(b) << 16);
}
__device__ __forceinline__ void split1(float x, __nv_bfloat16& h, __nv_bfloat16& l) {
    h = __float2bfloat16(x);
    l = __float2bfloat16(x - __bfloat162float(h));
}

// ---------------------------------------------------------------------------
// Fused one-time split: x + 4 weight matrices -> bf16 hi/lo
// ---------------------------------------------------------------------------
__global__ void split_all(const float* __restrict__ x,
                          const float* __restrict__ wq, const float* __restrict__ wk,
                          const float* __restrict__ wv, const float* __restrict__ wo,
                          __nv_bfloat16* __restrict__ XH, __nv_bfloat16* __restrict__ XL,
                          __nv_bfloat16* __restrict__ WH, __nv_bfloat16* __restrict__ WL)
{
    int i = blockIdx.x * blockDim.x + threadIdx.x;
    const int NX = CHUNK / 4;
    const int NW = (DIMc * DIMc) / 4;
    const float* src; __nv_bfloat16 *dh, *dl; int idx;
    if (i < NX) { src = x; dh = XH; dl = XL; idx = i; }
    else {
        int j = i - NX;
        if (j >= 4 * NW) return;
        int m = j >> 18; idx = j & (NW - 1);
        src = (m == 0) ? wq : (m == 1) ? wk : (m == 2) ? wv : wo;
        dh = WH + (size_t)m * DIMc * DIMc;
        dl = WL + (size_t)m * DIMc * DIMc;
    }
    float4 v = reinterpret_cast<const float4*>(src)[idx];
    __nv_bfloat16 h0,h1,h2,h3,l0,l1,l2,l3;
    split1(v.x,h0,l0); split1(v.y,h1,l1); split1(v.z,h2,l2); split1(v.w,h3,l3);
    reinterpret_cast<uint2*>(dh)[idx] = make_uint2(bcat(h0,h1), bcat(h2,h3));
    reinterpret_cast<uint2*>(dl)[idx] = make_uint2(bcat(l0,l1), bcat(l2,l3));
}

// ---------------------------------------------------------------------------
// Projection GEMM: cp.async 2-stage pipeline, bf16x3, dependency-spread MMAs.
// ---------------------------------------------------------------------------
#define SP 40
#define PBUF (128*SP)

template<int MODE>
__global__ __launch_bounds__(256, 2) void proj_mma(
    const __nv_bfloat16* __restrict__ Ah_g, const __nv_bfloat16* __restrict__ Al_g,
    const __nv_bfloat16* __restrict__ Wh_g, const __nv_bfloat16* __restrict__ Wl_g,
    float* __restrict__ OutF,
    __nv_bfloat16* __restrict__ Oh, __nv_bfloat16* __restrict__ Ol,
    const float* __restrict__ fc, const float* __restrict__ fs)
{
    extern __shared__ __align__(16) __nv_bfloat16 ps[];

    const int tid = threadIdx.x;
    const int warp = tid >> 5, lane = tid & 31;
    const int g = lane >> 3, r7 = lane & 7;
    const int mBase = blockIdx.y * 128, nBase = blockIdx.x * 128;
    const int wm = (warp & 3) * 32, wn = (warp >> 2) * 64;

    float c[2][8][4];
    #pragma unroll
    for (int i = 0; i < 2; i++)
        #pragma unroll
        for (int j = 0; j < 8; j++)
            #pragma unroll
            for (int k = 0; k < 4; k++) c[i][j][k] = 0.f;

    auto pload = [&](int s, int d0) {
        __nv_bfloat16* base = ps + s * 4 * PBUF;
        #pragma unroll
        for (int i = 0; i < 2; i++) {
            int ch = tid + 256 * i;
            int r = ch >> 2, c8 = (ch & 3) * 8;
            size_t ga = (size_t)(mBase + r) * DIMc + d0 + c8;
            size_t gw = (size_t)(nBase + r) * DIMc + d0 + c8;
            cpa16(sptr(&base[0*PBUF + r*SP + c8]), &Ah_g[ga]);
            cpa16(sptr(&base[1*PBUF + r*SP + c8]), &Al_g[ga]);
            cpa16(sptr(&base[2*PBUF + r*SP + c8]), &Wh_g[gw]);
            cpa16(sptr(&base[3*PBUF + r*SP + c8]), &Wl_g[gw]);
        }
    };

    pload(0, 0); cp_commit();

    for (int t = 0; t < DIMc / 32; t++) {
        int cur = t & 1;
        cp_wait0();
        __syncthreads();
        if (t + 1 < DIMc / 32) { pload(cur ^ 1, (t + 1) * 32); cp_commit(); }

        __nv_bfloat16* Ah = ps + cur * 4 * PBUF;
        __nv_bfloat16* Al = Ah + PBUF;
        __nv_bfloat16* Bh = Ah + 2 * PBUF;
        __nv_bfloat16* Bl = Ah + 3 * PBUF;

        #pragma unroll
        for (int kk = 0; kk < 32; kk += 16) {
            unsigned ah[2][4], al[2][4];
            #pragma unroll
            for (int mt = 0; mt < 2; mt++) {
                int row = wm + mt*16 + (g & 1)*8 + r7;
                int col = kk + (g >> 1)*8;
                ldsm4(sptr(&Ah[row*SP + col]), ah[mt]);
                ldsm4(sptr(&Al[row*SP + col]), al[mt]);
            }
            #pragma unroll
            for (int np = 0; np < 4; np++) {
                int row = wn + np*16 + (g >> 1)*8 + r7;
                int col = kk + (g & 1)*8;
                unsigned bh[4], bl[4];
                ldsm4(sptr(&Bh[row*SP + col]), bh);
                ldsm4(sptr(&Bl[row*SP + col]), bl);
                float* c0 = c[0][np*2]; float* c1 = c[0][np*2+1];
                float* c2 = c[1][np*2]; float* c3 = c[1][np*2+1];
                // spread: same accumulator revisited only every 4 MMAs
                mma_bf16(c0, ah[0], bh[0], bh[1]);
                mma_bf16(c1, ah[0], bh[2], bh[3]);
                mma_bf16(c2, ah[1], bh[0], bh[1]);
                mma_bf16(c3, ah[1], bh[2], bh[3]);
                mma_bf16(c0, al[0], bh[0], bh[1]);
                mma_bf16(c1, al[0], bh[2], bh[3]);
                mma_bf16(c2, al[1], bh[0], bh[1]);
                mma_bf16(c3, al[1], bh[2], bh[3]);
                mma_bf16(c0, ah[0], bl[0], bl[1]);
                mma_bf16(c1, ah[0], bl[2], bl[3]);
                mma_bf16(c2, ah[1], bl[0], bl[1]);
                mma_bf16(c3, ah[1], bl[2], bl[3]);
            }
        }
    }

    #pragma unroll
    for (int mt = 0; mt < 2; mt++) {
        int row = mBase + wm + mt*16 + (lane >> 2);
        #pragma unroll
        for (int nt = 0; nt < 8; nt++) {
            int col = nBase + wn + nt*8 + (lane & 3)*2;
            float v0 = c[mt][nt][0], v1 = c[mt][nt][1];
            float v2 = c[mt][nt][2], v3 = c[mt][nt][3];
            if (MODE == 2) {
                int i = (col & 63) >> 1;
                int s0 = row & (Sc-1), s1 = (row + 8) & (Sc-1);
                float c0 = fc[s0*32 + i], sn0 = fs[s0*32 + i];
                float c1 = fc[s1*32 + i], sn1 = fs[s1*32 + i];
                float a0 = v0, b0 = v1, a1 = v2, b1 = v3;
                v0 = a0*c0 - b0*sn0; v1 = a0*sn0 + b0*c0;
                v2 = a1*c1 - b1*sn1; v3 = a1*sn1 + b1*c1;
            }
            if (MODE == 0) {
                *(float2*)(OutF + (size_t)row * DIMc + col)     = make_float2(v0, v1);
                *(float2*)(OutF + (size_t)(row+8) * DIMc + col) = make_float2(v2, v3);
            } else {
                __nv_bfloat16 h0,l0,h1,l1,h2,l2,h3,l3;
                split1(v0,h0,l0); split1(v1,h1,l1); split1(v2,h2,l2); split1(v3,h3,l3);
                *(unsigned*)&Oh[(size_t)row * DIMc + col]     = bcat(h0,h1);
                *(unsigned*)&Ol[(size_t)row * DIMc + col]     = bcat(l0,l1);
                *(unsigned*)&Oh[(size_t)(row+8) * DIMc + col] = bcat(h2,h3);
                *(unsigned*)&Ol[(size_t)(row+8) * DIMc + col] = bcat(l2,l3);
            }
        }
    }
}

// ---------------------------------------------------------------------------
// Attention: two-pass, pipelined, dependency-spread MMAs.
// Pass 2 uses Q-hi only (hh + hl terms): weights-only precision, saves 1/3 MMA.
// ---------------------------------------------------------------------------
#define SQa 72
#define SEa 136
#define QB (128*SQa)
#define EB (128*SEa)

__global__ __launch_bounds__(512, 1) void attn_mma(
    float* __restrict__ attn,
    const __nv_bfloat16* __restrict__ Qh_g, const __nv_bfloat16* __restrict__ Ql_g,
    const __nv_bfloat16* __restrict__ Kh_g, const __nv_bfloat16* __restrict__ Kl_g,
    const __nv_bfloat16* __restrict__ Vh_g, const __nv_bfloat16* __restrict__ Vl_g,
    __nv_bfloat16* __restrict__ Ch_g, __nv_bfloat16* __restrict__ Cl_g)
{
    extern __shared__ __align__(16) __nv_bfloat16 sm[];
    __nv_bfloat16* Qh = sm;
    __nv_bfloat16* Ql = Qh + QB;
    __nv_bfloat16* Kst = Ql + QB;
    __nv_bfloat16* Vh = Kst + 4*QB;
    __nv_bfloat16* Vl = Vh + QB;
    __nv_bfloat16* Eh = Vl + QB;
    __nv_bfloat16* El = Eh + EB;
    float* rowsum = (float*)(El + EB);

    const int tid = threadIdx.x;
    const int warp = tid >> 5, lane = tid & 31;
    const int g = lane >> 3, r7 = lane & 7;
    const int qBase = blockIdx.x * 128;
    const int h = blockIdx.y, b = blockIdx.z;

    const size_t qOff = (size_t)(b * Sc + qBase) * DIMc + h * HDc;
    const size_t kvOff = (size_t)b * Sc * DIMc + h * HDc;
    float* arow = attn + ((size_t)(b * NHc + h) * Sc + qBase) * Sc;

    if (tid < 128) rowsum[tid] = 0.f;

    auto kload = [&](int s, int kt) {
        __nv_bfloat16* KH = Kst + s * 2 * QB;
        __nv_bfloat16* KL = KH + QB;
        #pragma unroll
        for (int i = 0; i < 2; i++) {
            int ch = tid + 512 * i;
            int r = ch >> 3, c8 = (ch & 7) * 8;
            size_t gk = kvOff + (size_t)(kt + r) * DIMc + c8;
            cpa16(sptr(&KH[r*SQa + c8]), &Kh_g[gk]);
            cpa16(sptr(&KL[r*SQa + c8]), &Kl_g[gk]);
        }
    };
    auto vload = [&](int kt) {
        #pragma unroll
        for (int i = 0; i < 2; i++) {
            int ch = tid + 512 * i;
            int r = ch >> 3, c8 = (ch & 7) * 8;
            size_t gk = kvOff + (size_t)(kt + r) * DIMc + c8;
            cpa16(sptr(&Vh[r*SQa + c8]), &Vh_g[gk]);
            cpa16(sptr(&Vl[r*SQa + c8]), &Vl_g[gk]);
        }
    };

    #pragma unroll
    for (int i = 0; i < 2; i++) {
        int ch = tid + 512 * i;
        int r = ch >> 3, c8 = (ch & 7) * 8;
        size_t gq = qOff + (size_t)r * DIMc + c8;
        cpa16(sptr(&Qh[r*SQa + c8]), &Qh_g[gq]);
        cpa16(sptr(&Ql[r*SQa + c8]), &Ql_g[gq]);
    }
    kload(0, 0);
    cp_commit();

    const int wm = (warp & 3) * 32;
    const int wq = warp >> 2;
    const int wn = wq * 32;
    const int wd = wq * 16;

    float ctx[2][2][4] = {};
    float rs[4] = {0.f, 0.f, 0.f, 0.f};

    // ---------------- pass 1 ----------------
    for (int t = 0; t < Sc / 128; t++) {
        const int cur = t & 1;
        const int kt = t * 128;
        cp_wait0();
        __syncthreads();
        vload(kt); cp_commit();
        const bool pre = (t + 1 < Sc / 128);
        if (pre) { kload(cur ^ 1, kt + 128); cp_commit(); }

        __nv_bfloat16* KH = Kst + cur * 2 * QB;
        __nv_bfloat16* KL = KH + QB;

        float s[2][4][4] = {};
        #pragma unroll
        for (int kk = 0; kk < 64; kk += 16) {
            unsigned ah[2][4], al[2][4];
            #pragma unroll
            for (int mt = 0; mt < 2; mt++) {
                int row = wm + mt*16 + (g & 1)*8 + r7;
                int col = kk + (g >> 1)*8;
                ldsm4(sptr(Qh + row*SQa + col), ah[mt]);
                ldsm4(sptr(Ql + row*SQa + col), al[mt]);
            }
            #pragma unroll
            for (int np = 0; np < 2; np++) {
                int row = wn + np*16 + (g >> 1)*8 + r7;
                int col = kk + (g & 1)*8;
                unsigned bh[4], bl[4];
                ldsm4(sptr(KH + row*SQa + col), bh);
                ldsm4(sptr(KL + row*SQa + col), bl);
                float* s0 = s[0][np*2]; float* s1 = s[0][np*2+1];
                float* s2 = s[1][np*2]; float* s3 = s[1][np*2+1];
                mma_bf16(s0, ah[0], bh[0], bh[1]);
                mma_bf16(s1, ah[0], bh[2], bh[3]);
                mma_bf16(s2, ah[1], bh[0], bh[1]);
                mma_bf16(s3, ah[1], bh[2], bh[3]);
                mma_bf16(s0, al[0], bh[0], bh[1]);
                mma_bf16(s1, al[0], bh[2], bh[3]);
                mma_bf16(s2, al[1], bh[0], bh[1]);
                mma_bf16(s3, al[1], bh[2], bh[3]);
                mma_bf16(s0, ah[0], bl[0], bl[1]);
                mma_bf16(s1, ah[0], bl[2], bl[3]);
                mma_bf16(s2, ah[1], bl[0], bl[1]);
                mma_bf16(s3, ah[1], bl[2], bl[3]);
            }
        }

        if (pre) cp_wait1(); else cp_wait0();
        __syncthreads();

        #pragma unroll
        for (int mt = 0; mt < 2; mt++) {
            int row0 = wm + mt*16 + (lane >> 2);
            #pragma unroll
            for (int nt = 0; nt < 4; nt++) {
                int col = wn + nt*8 + (lane & 3)*2;
                float e0 = __expf(s[mt][nt][0] * 0.125f);
                float e1 = __expf(s[mt][nt][1] * 0.125f);
                float e2 = __expf(s[mt][nt][2] * 0.125f);
                float e3 = __expf(s[mt][nt][3] * 0.125f);
                rs[mt*2+0] += e0 + e1;
                rs[mt*2+1] += e2 + e3;
                __nv_bfloat16 h0,l0,h1,l1,h2,l2,h3,l3;
                split1(e0,h0,l0); split1(e1,h1,l1); split1(e2,h2,l2); split1(e3,h3,l3);
                *(unsigned*)(Eh + row0*SEa + col)     = bcat(h0, h1);
                *(unsigned*)(Eh + (row0+8)*SEa + col) = bcat(h2, h3);
                *(unsigned*)(El + row0*SEa + col)     = bcat(l0, l1);
                *(unsigned*)(El + (row0+8)*SEa + col) = bcat(l2, l3);
            }
        }
        __syncthreads();

        #pragma unroll
        for (int kk = 0; kk < 128; kk += 16) {
            unsigned ah[2][4], al[2][4];
            #pragma unroll
            for (int mt = 0; mt < 2; mt++) {
                int row = wm + mt*16 + (g & 1)*8 + r7;
                int col = kk + (g >> 1)*8;
                ldsm4(sptr(Eh + row*SEa + col), ah[mt]);
                ldsm4(sptr(El + row*SEa + col), al[mt]);
            }
            int vrow = kk + (g & 1)*8 + r7;
            int vcol = wd + (g >> 1)*8;
            unsigned bh[4], bl[4];
            ldsm4t(sptr(Vh + vrow*SQa + vcol), bh);
            ldsm4t(sptr(Vl + vrow*SQa + vcol), bl);
            float* c0 = ctx[0][0]; float* c1 = ctx[0][1];
            float* c2 = ctx[1][0]; float* c3 = ctx[1][1];
            mma_bf16(c0, ah[0], bh[0], bh[1]);
            mma_bf16(c1, ah[0], bh[2], bh[3]);
            mma_bf16(c2, ah[1], bh[0], bh[1]);
            mma_bf16(c3, ah[1], bh[2], bh[3]);
            mma_bf16(c0, al[0], bh[0], bh[1]);
            mma_bf16(c1, al[0], bh[2], bh[3]);
            mma_bf16(c2, al[1], bh[0], bh[1]);
            mma_bf16(c3, al[1], bh[2], bh[3]);
            mma_bf16(c0, ah[0], bl[0], bl[1]);
            mma_bf16(c1, ah[0], bl[2], bl[3]);
            mma_bf16(c2, ah[1], bl[0], bl[1]);
            mma_bf16(c3, ah[1], bl[2], bl[3]);
        }
    }

    #pragma unroll
    for (int mt = 0; mt < 2; mt++) {
        int row0 = wm + mt*16 + (lane >> 2);
        atomicAdd(&rowsum[row0],     rs[mt*2+0]);
        atomicAdd(&rowsum[row0 + 8], rs[mt*2+1]);
    }
    __syncthreads();
    if (tid < 128) rowsum[tid] = 1.0f / rowsum[tid];
    __syncthreads();

    #pragma unroll
    for (int mt = 0; mt < 2; mt++) {
        int row0 = wm + mt*16 + (lane >> 2);
        float iv0 = rowsum[row0], iv1 = rowsum[row0 + 8];
        #pragma unroll
        for (int nt = 0; nt < 2; nt++) {
            int col = wd + nt*8 + (lane & 3)*2;
            float v0 = ctx[mt][nt][0] * iv0, v1 = ctx[mt][nt][1] * iv0;
            float v2 = ctx[mt][nt][2] * iv1, v3 = ctx[mt][nt][3] * iv1;
            __nv_bfloat16 h0,l0,h1,l1,h2,l2,h3,l3;
            split1(v0,h0,l0); split1(v1,h1,l1); split1(v2,h2,l2); split1(v3,h3,l3);
            size_t o0 = qOff + (size_t)row0 * DIMc + col;
            size_t o1 = qOff + (size_t)(row0+8) * DIMc + col;
            *(unsigned*)&Ch_g[o0] = bcat(h0,h1);
            *(unsigned*)&Cl_g[o0] = bcat(l0,l1);
            *(unsigned*)&Ch_g[o1] = bcat(h2,h3);
            *(unsigned*)&Cl_g[o1] = bcat(l2,l3);
        }
    }

    float invr[2][2];
    #pragma unroll
    for (int mt = 0; mt < 2; mt++) {
        invr[mt][0] = rowsum[wm + mt*16 + (lane >> 2)];
        invr[mt][1] = rowsum[wm + mt*16 + 8 + (lane >> 2)];
    }
    __syncthreads();

    // ---------------- pass 2 (Q-hi only: hh + hl) ----------------
    kload(0, 0); cp_commit();
    for (int t = 0; t < Sc / 128; t++) {
        const int cur = t & 1;
        const int kt = t * 128;
        cp_wait0();
        __syncthreads();
        if (t + 1 < Sc / 128) { kload(cur ^ 1, kt + 128); cp_commit(); }

        __nv_bfloat16* KH = Kst + cur * 2 * QB;
        __nv_bfloat16* KL = KH + QB;

        float s[2][4][4] = {};
        #pragma unroll
        for (int kk = 0; kk < 64; kk += 16) {
            unsigned ah[2][4];
            #pragma unroll
            for (int mt = 0; mt < 2; mt++) {
                int row = wm + mt*16 + (g & 1)*8 + r7;
                int col = kk + (g >> 1)*8;
                ldsm4(sptr(Qh + row*SQa + col), ah[mt]);
            }
            #pragma unroll
            for (int np = 0; np < 2; np++) {
                int row = wn + np*16 + (g >> 1)*8 + r7;
                int col = kk + (g & 1)*8;
                unsigned bh[4], bl[4];
                ldsm4(sptr(KH + row*SQa + col), bh);
                ldsm4(sptr(KL + row*SQa + col), bl);
                float* s0 = s[0][np*2]; float* s1 = s[0][np*2+1];
                float* s2 = s[1][np*2]; float* s3 = s[1][np*2+1];
                mma_bf16(s0, ah[0], bh[0], bh[1]);
                mma_bf16(s1, ah[0], bh[2], bh[3]);
                mma_bf16(s2, ah[1], bh[0], bh[1]);
                mma_bf16(s3, ah[1], bh[2], bh[3]);
                mma_bf16(s0, ah[0], bl[0], bl[1]);
                mma_bf16(s1, ah[0], bl[2], bl[3]);
                mma_bf16(s2, ah[1], bl[0], bl[1]);
                mma_bf16(s3, ah[1], bl[2], bl[3]);
            }
        }

        #pragma unroll
        for (int mt = 0; mt < 2; mt++) {
            int row0 = wm + mt*16 + (lane >> 2);
            #pragma unroll
            for (int nt = 0; nt < 4; nt++) {
                int col = wn + nt*8 + (lane & 3)*2;
                float e0 = __expf(s[mt][nt][0] * 0.125f) * invr[mt][0];
                float e1 = __expf(s[mt][nt][1] * 0.125f) * invr[mt][0];
                float e2 = __expf(s[mt][nt][2] * 0.125f) * invr[mt][1];
                float e3 = __expf(s[mt][nt][3] * 0.125f) * invr[mt][1];
                *(float2*)(arow + (size_t)row0 * Sc + kt + col)     = make_float2(e0, e1);
                *(float2*)(arow + (size_t)(row0+8) * Sc + kt + col) = make_float2(e2, e3);
            }
        }
    }
}

// ---------------------------------------------------------------------------
// Launcher
// ---------------------------------------------------------------------------
extern "C" void kernel_launch(void* const* d_in, const int* in_sizes, int n_in,
                              void* d_out, int out_size)
{
    const float* x  = (const float*)d_in[0];
    const float* wq = (const float*)d_in[1];
    const float* wk = (const float*)d_in[2];
    const float* wv = (const float*)d_in[3];
    const float* wo = (const float*)d_in[4];
    const float* fc = (const float*)d_in[5];
    const float* fs = (const float*)d_in[6];

    float* out  = (float*)d_out;
    float* attn = out + (size_t)Bc * Sc * DIMc;

    __nv_bfloat16* buf;
    cudaGetSymbolAddress((void**)&buf, g_buf);
    const size_t WM = (size_t)DIMc * DIMc;
    __nv_bfloat16* XH = buf;
    __nv_bfloat16* XL = buf + 1ull*CHUNK;
    __nv_bfloat16* WH = buf + 2ull*CHUNK;
    __nv_bfloat16* WL = buf + 3ull*CHUNK;
    __nv_bfloat16* QH = buf + 4ull*CHUNK;
    __nv_bfloat16* QL = buf + 5ull*CHUNK;
    __nv_bfloat16* KH = buf + 6ull*CHUNK;
    __nv_bfloat16* KL = buf + 7ull*CHUNK;
    __nv_bfloat16* VH = buf + 8ull*CHUNK;
    __nv_bfloat16* VL = buf + 9ull*CHUNK;
    __nv_bfloat16* CH = buf + 10ull*CHUNK;
    __nv_bfloat16* CL = buf + 11ull*CHUNK;

    const int projSmem = 2 * 4 * PBUF * 2;
    cudaFuncSetAttribute(proj_mma<0>, cudaFuncAttributeMaxDynamicSharedMemorySize, projSmem);
    cudaFuncSetAttribute(proj_mma<1>, cudaFuncAttributeMaxDynamicSharedMemorySize, projSmem);
    cudaFuncSetAttribute(proj_mma<2>, cudaFuncAttributeMaxDynamicSharedMemorySize, projSmem);
    const int attnSmem = (8 * QB + 2 * EB) * 2 + 128 * 4;
    cudaFuncSetAttribute(attn_mma, cudaFuncAttributeMaxDynamicSharedMemorySize, attnSmem);

    int nSplit = CHUNK / 4 + DIMc * DIMc;
    split_all<<<(nSplit + 255) / 256, 256>>>(x, wq, wk, wv, wo, XH, XL, WH, WL);

    dim3 pgrid(DIMc / 128, TTOT / 128);
    proj_mma<2><<<pgrid, 256, projSmem>>>(XH, XL, WH + 0*WM, WL + 0*WM, nullptr, QH, QL, fc, fs);
    proj_mma<2><<<pgrid, 256, projSmem>>>(XH, XL, WH + 1*WM, WL + 1*WM, nullptr, KH, KL, fc, fs);
    proj_mma<1><<<pgrid, 256, projSmem>>>(XH, XL, WH + 2*WM, WL + 2*WM, nullptr, VH, VL, nullptr, nullptr);

    attn_mma<<<dim3(Sc/128, NHc, Bc), 512, attnSmem>>>(attn, QH, QL, KH, KL, VH, VL, CH, CL);

    proj_mma<0><<<pgrid, 256, projSmem>>>(CH, CL, WH + 3*WM, WL + 3*WM, out, nullptr, nullptr, nullptr, nullptr);
}

// round 7
// speedup vs baseline: 2.3004x; 2.0091x over previous
#include <cuda_runtime.h>
#include <cuda_fp16.h>
#include <cstdint>

#define Bc   2
#define Sc   2048
#define DIMc 1024
#define NHc  16
#define HDc  64
#define TTOT (Bc*Sc)
#define CHUNK (TTOT*DIMc)          // 4,194,304 elements

// Scratch arena (fp16), CHUNK units: 0 X | 1 W(4 mats) | 2 Q | 3 K | 4 V | 5 C
__device__ __half g_buf[6ull * CHUNK];

// ---------------------------------------------------------------------------
// helpers
// ---------------------------------------------------------------------------
__device__ __forceinline__ unsigned sptr(const void* p) {
    return (unsigned)__cvta_generic_to_shared(p);
}
__device__ __forceinline__ void cpa16(unsigned d, const void* s) {
    asm volatile("cp.async.cg.shared.global [%0], [%1], 16;" :: "r"(d), "l"(s));
}
__device__ __forceinline__ void cp_commit() { asm volatile("cp.async.commit_group;"); }
__device__ __forceinline__ void cp_wait0()  { asm volatile("cp.async.wait_group 0;"); }
__device__ __forceinline__ void cp_wait1()  { asm volatile("cp.async.wait_group 1;"); }

__device__ __forceinline__ void ldsm4(unsigned a, unsigned* r) {
    asm volatile("ldmatrix.sync.aligned.m8n8.x4.shared.b16 {%0,%1,%2,%3},[%4];"
        : "=r"(r[0]), "=r"(r[1]), "=r"(r[2]), "=r"(r[3]) : "r"(a));
}
__device__ __forceinline__ void ldsm4t(unsigned a, unsigned* r) {
    asm volatile("ldmatrix.sync.aligned.m8n8.x4.trans.shared.b16 {%0,%1,%2,%3},[%4];"
        : "=r"(r[0]), "=r"(r[1]), "=r"(r[2]), "=r"(r[3]) : "r"(a));
}
__device__ __forceinline__ void mma_f16(float* c, const unsigned* a, unsigned b0, unsigned b1) {
    asm volatile(
        "mma.sync.aligned.m16n8k16.row.col.f32.f16.f16.f32 "
        "{%0,%1,%2,%3},{%4,%5,%6,%7},{%8,%9},{%0,%1,%2,%3};"
        : "+f"(c[0]), "+f"(c[1]), "+f"(c[2]), "+f"(c[3])
        : "r"(a[0]), "r"(a[1]), "r"(a[2]), "r"(a[3]), "r"(b0), "r"(b1));
}
// pack two fp32 -> f16x2 register (lo = v0, hi = v1)
__device__ __forceinline__ unsigned packh2(float v0, float v1) {
    unsigned r;
    asm("cvt.rn.f16x2.f32 %0, %1, %2;" : "=r"(r) : "f"(v1), "f"(v0));
    return r;
}

// ---------------------------------------------------------------------------
// One-time convert: x + 4 weight matrices -> fp16
// ---------------------------------------------------------------------------
__global__ void cvt_all(const float* __restrict__ x,
                        const float* __restrict__ wq, const float* __restrict__ wk,
                        const float* __restrict__ wv, const float* __restrict__ wo,
                        __half* __restrict__ X, __half* __restrict__ W)
{
    int i = blockIdx.x * blockDim.x + threadIdx.x;
    const int NX = CHUNK / 4;                 // 1,048,576 float4s in x
    const int NW = (DIMc * DIMc) / 4;         // 262,144 per weight
    const float* src; __half* dst; int idx;
    if (i < NX) { src = x; dst = X; idx = i; }
    else {
        int j = i - NX;
        if (j >= 4 * NW) return;
        int m = j >> 18; idx = j & (NW - 1);
        src = (m == 0) ? wq : (m == 1) ? wk : (m == 2) ? wv : wo;
        dst = W + (size_t)m * DIMc * DIMc;
    }
    float4 v = reinterpret_cast<const float4*>(src)[idx];
    reinterpret_cast<uint2*>(dst)[idx] = make_uint2(packh2(v.x, v.y), packh2(v.z, v.w));
}

// ---------------------------------------------------------------------------
// Projection GEMM (fp16 x1): Out[m][n] = sum_k A[m][k]*W[n][k]
// BM=BN=128, BK=32, 256 thr, 2-stage cp.async.
// MODE 0: fp32 out; MODE 1: fp16 out; MODE 2: rope + fp16 out.
// ---------------------------------------------------------------------------
#define SP 40            // smem row stride (halfs): 80B
#define PBUF (128*SP)    // elems per matrix buffer

template<int MODE>
__global__ __launch_bounds__(256, 2) void proj_mma(
    const __half* __restrict__ A_g, const __half* __restrict__ W_g,
    float* __restrict__ OutF, __half* __restrict__ O_g,
    const float* __restrict__ fc, const float* __restrict__ fs)
{
    extern __shared__ __align__(16) __half ps[];   // 2 stages x 2 bufs x PBUF

    const int tid = threadIdx.x;
    const int warp = tid >> 5, lane = tid & 31;
    const int g = lane >> 3, r7 = lane & 7;
    const int mBase = blockIdx.y * 128, nBase = blockIdx.x * 128;
    const int wm = (warp & 3) * 32, wn = (warp >> 2) * 64;

    float c[2][8][4];
    #pragma unroll
    for (int i = 0; i < 2; i++)
        #pragma unroll
        for (int j = 0; j < 8; j++)
            #pragma unroll
            for (int k = 0; k < 4; k++) c[i][j][k] = 0.f;

    auto pload = [&](int s, int d0) {
        __half* base = ps + s * 2 * PBUF;
        #pragma unroll
        for (int i = 0; i < 2; i++) {
            int ch = tid + 256 * i;            // 512 chunks: 128 rows x 4
            int r = ch >> 2, c8 = (ch & 3) * 8;
            size_t ga = (size_t)(mBase + r) * DIMc + d0 + c8;
            size_t gw = (size_t)(nBase + r) * DIMc + d0 + c8;
            cpa16(sptr(&base[r*SP + c8]), &A_g[ga]);
            cpa16(sptr(&base[PBUF + r*SP + c8]), &W_g[gw]);
        }
    };

    pload(0, 0); cp_commit();

    for (int t = 0; t < DIMc / 32; t++) {
        int cur = t & 1;
        cp_wait0();
        __syncthreads();
        if (t + 1 < DIMc / 32) { pload(cur ^ 1, (t + 1) * 32); cp_commit(); }

        __half* Ah = ps + cur * 2 * PBUF;
        __half* Bh = Ah + PBUF;

        #pragma unroll
        for (int kk = 0; kk < 32; kk += 16) {
            unsigned ah[2][4];
            #pragma unroll
            for (int mt = 0; mt < 2; mt++) {
                int row = wm + mt*16 + (g & 1)*8 + r7;
                int col = kk + (g >> 1)*8;
                ldsm4(sptr(&Ah[row*SP + col]), ah[mt]);
            }
            #pragma unroll
            for (int np = 0; np < 4; np++) {
                int row = wn + np*16 + (g >> 1)*8 + r7;
                int col = kk + (g & 1)*8;
                unsigned bh[4];
                ldsm4(sptr(&Bh[row*SP + col]), bh);
                mma_f16(c[0][np*2],   ah[0], bh[0], bh[1]);
                mma_f16(c[0][np*2+1], ah[0], bh[2], bh[3]);
                mma_f16(c[1][np*2],   ah[1], bh[0], bh[1]);
                mma_f16(c[1][np*2+1], ah[1], bh[2], bh[3]);
            }
        }
    }

    #pragma unroll
    for (int mt = 0; mt < 2; mt++) {
        int row = mBase + wm + mt*16 + (lane >> 2);
        #pragma unroll
        for (int nt = 0; nt < 8; nt++) {
            int col = nBase + wn + nt*8 + (lane & 3)*2;
            float v0 = c[mt][nt][0], v1 = c[mt][nt][1];
            float v2 = c[mt][nt][2], v3 = c[mt][nt][3];
            if (MODE == 2) {
                int i = (col & 63) >> 1;
                int s0 = row & (Sc-1), s1 = (row + 8) & (Sc-1);
                float c0 = fc[s0*32 + i], sn0 = fs[s0*32 + i];
                float c1 = fc[s1*32 + i], sn1 = fs[s1*32 + i];
                float a0 = v0, b0 = v1, a1 = v2, b1 = v3;
                v0 = a0*c0 - b0*sn0; v1 = a0*sn0 + b0*c0;
                v2 = a1*c1 - b1*sn1; v3 = a1*sn1 + b1*c1;
            }
            if (MODE == 0) {
                *(float2*)(OutF + (size_t)row * DIMc + col)     = make_float2(v0, v1);
                *(float2*)(OutF + (size_t)(row+8) * DIMc + col) = make_float2(v2, v3);
            } else {
                *(unsigned*)&O_g[(size_t)row * DIMc + col]     = packh2(v0, v1);
                *(unsigned*)&O_g[(size_t)(row+8) * DIMc + col] = packh2(v2, v3);
            }
        }
    }
}

// ---------------------------------------------------------------------------
// Attention (fp16 x1): two-pass, cp.async pipelined.
// Pass 1: scores -> exp -> rowsum + PV (ctx). Pass 2: recompute scores,
// write normalized weights.
// ---------------------------------------------------------------------------
#define SQa 72     // 144B rows (LDSM conflict-free)
#define SEa 136    // 272B rows
#define QB (128*SQa)   // 9216 halfs per 128x64 buffer
#define EB (128*SEa)

__global__ __launch_bounds__(512, 1) void attn_mma(
    float* __restrict__ attn,
    const __half* __restrict__ Q_g, const __half* __restrict__ K_g,
    const __half* __restrict__ V_g, __half* __restrict__ C_g)
{
    extern __shared__ __align__(16) __half sm[];
    __half* Qh = sm;                 // QB
    __half* Kst = Qh + QB;           // 2 stages x QB
    __half* Vh = Kst + 2*QB;         // QB
    __half* Eh = Vh + QB;            // EB
    float* rowsum = (float*)(Eh + EB);

    const int tid = threadIdx.x;
    const int warp = tid >> 5, lane = tid & 31;
    const int g = lane >> 3, r7 = lane & 7;
    const int qBase = blockIdx.x * 128;
    const int h = blockIdx.y, b = blockIdx.z;

    const size_t qOff = (size_t)(b * Sc + qBase) * DIMc + h * HDc;
    const size_t kvOff = (size_t)b * Sc * DIMc + h * HDc;
    float* arow = attn + ((size_t)(b * NHc + h) * Sc + qBase) * Sc;

    if (tid < 128) rowsum[tid] = 0.f;

    auto kload = [&](int s, int kt) {
        __half* KH = Kst + s * QB;
        #pragma unroll
        for (int i = 0; i < 2; i++) {
            int ch = tid + 512 * i;
            int r = ch >> 3, c8 = (ch & 7) * 8;
            cpa16(sptr(&KH[r*SQa + c8]), &K_g[kvOff + (size_t)(kt + r) * DIMc + c8]);
        }
    };
    auto vload = [&](int kt) {
        #pragma unroll
        for (int i = 0; i < 2; i++) {
            int ch = tid + 512 * i;
            int r = ch >> 3, c8 = (ch & 7) * 8;
            cpa16(sptr(&Vh[r*SQa + c8]), &V_g[kvOff + (size_t)(kt + r) * DIMc + c8]);
        }
    };

    // prologue: Q + K_0
    #pragma unroll
    for (int i = 0; i < 2; i++) {
        int ch = tid + 512 * i;
        int r = ch >> 3, c8 = (ch & 7) * 8;
        cpa16(sptr(&Qh[r*SQa + c8]), &Q_g[qOff + (size_t)r * DIMc + c8]);
    }
    kload(0, 0);
    cp_commit();

    const int wm = (warp & 3) * 32;
    const int wq = warp >> 2;          // 0..3
    const int wn = wq * 32;
    const int wd = wq * 16;

    float ctx[2][2][4] = {};
    float rs[4] = {0.f, 0.f, 0.f, 0.f};

    // ---------------- pass 1 ----------------
    for (int t = 0; t < Sc / 128; t++) {
        const int cur = t & 1;
        const int kt = t * 128;
        cp_wait0();
        __syncthreads();                 // K_t (and Q) visible; prev PV done
        vload(kt); cp_commit();          // group: V_t
        const bool pre = (t + 1 < Sc / 128);
        if (pre) { kload(cur ^ 1, kt + 128); cp_commit(); }   // group: K_{t+1}

        __half* KH = Kst + cur * QB;

        float s[2][4][4] = {};
        #pragma unroll
        for (int kk = 0; kk < 64; kk += 16) {
            unsigned ah[2][4];
            #pragma unroll
            for (int mt = 0; mt < 2; mt++) {
                int row = wm + mt*16 + (g & 1)*8 + r7;
                int col = kk + (g >> 1)*8;
                ldsm4(sptr(Qh + row*SQa + col), ah[mt]);
            }
            #pragma unroll
            for (int np = 0; np < 2; np++) {
                int row = wn + np*16 + (g >> 1)*8 + r7;
                int col = kk + (g & 1)*8;
                unsigned bh[4];
                ldsm4(sptr(KH + row*SQa + col), bh);
                mma_f16(s[0][np*2],   ah[0], bh[0], bh[1]);
                mma_f16(s[0][np*2+1], ah[0], bh[2], bh[3]);
                mma_f16(s[1][np*2],   ah[1], bh[0], bh[1]);
                mma_f16(s[1][np*2+1], ah[1], bh[2], bh[3]);
            }
        }

        if (pre) cp_wait1(); else cp_wait0();   // V_t arrived
        __syncthreads();                        // V visible; E free

        #pragma unroll
        for (int mt = 0; mt < 2; mt++) {
            int row0 = wm + mt*16 + (lane >> 2);
            #pragma unroll
            for (int nt = 0; nt < 4; nt++) {
                int col = wn + nt*8 + (lane & 3)*2;
                float e0 = __expf(s[mt][nt][0] * 0.125f);
                float e1 = __expf(s[mt][nt][1] * 0.125f);
                float e2 = __expf(s[mt][nt][2] * 0.125f);
                float e3 = __expf(s[mt][nt][3] * 0.125f);
                rs[mt*2+0] += e0 + e1;
                rs[mt*2+1] += e2 + e3;
                *(unsigned*)(Eh + row0*SEa + col)     = packh2(e0, e1);
                *(unsigned*)(Eh + (row0+8)*SEa + col) = packh2(e2, e3);
            }
        }
        __syncthreads();   // E visible

        #pragma unroll
        for (int kk = 0; kk < 128; kk += 16) {
            unsigned ah[2][4];
            #pragma unroll
            for (int mt = 0; mt < 2; mt++) {
                int row = wm + mt*16 + (g & 1)*8 + r7;
                int col = kk + (g >> 1)*8;
                ldsm4(sptr(Eh + row*SEa + col), ah[mt]);
            }
            int vrow = kk + (g & 1)*8 + r7;
            int vcol = wd + (g >> 1)*8;
            unsigned bh[4];
            ldsm4t(sptr(Vh + vrow*SQa + vcol), bh);
            mma_f16(ctx[0][0], ah[0], bh[0], bh[1]);
            mma_f16(ctx[0][1], ah[0], bh[2], bh[3]);
            mma_f16(ctx[1][0], ah[1], bh[0], bh[1]);
            mma_f16(ctx[1][1], ah[1], bh[2], bh[3]);
        }
    }

    // rowsum -> inverse
    #pragma unroll
    for (int mt = 0; mt < 2; mt++) {
        int row0 = wm + mt*16 + (lane >> 2);
        atomicAdd(&rowsum[row0],     rs[mt*2+0]);
        atomicAdd(&rowsum[row0 + 8], rs[mt*2+1]);
    }
    __syncthreads();
    if (tid < 128) rowsum[tid] = 1.0f / rowsum[tid];
    __syncthreads();

    // ctx epilogue: normalize + fp16 store
    #pragma unroll
    for (int mt = 0; mt < 2; mt++) {
        int row0 = wm + mt*16 + (lane >> 2);
        float iv0 = rowsum[row0], iv1 = rowsum[row0 + 8];
        #pragma unroll
        for (int nt = 0; nt < 2; nt++) {
            int col = wd + nt*8 + (lane & 3)*2;
            size_t o0 = qOff + (size_t)row0 * DIMc + col;
            size_t o1 = qOff + (size_t)(row0+8) * DIMc + col;
            *(unsigned*)&C_g[o0] = packh2(ctx[mt][nt][0] * iv0, ctx[mt][nt][1] * iv0);
            *(unsigned*)&C_g[o1] = packh2(ctx[mt][nt][2] * iv1, ctx[mt][nt][3] * iv1);
        }
    }

    float invr[2][2];
    #pragma unroll
    for (int mt = 0; mt < 2; mt++) {
        invr[mt][0] = rowsum[wm + mt*16 + (lane >> 2)];
        invr[mt][1] = rowsum[wm + mt*16 + 8 + (lane >> 2)];
    }
    __syncthreads();

    // ---------------- pass 2: recompute scores, write normalized ----------------
    kload(0, 0); cp_commit();
    for (int t = 0; t < Sc / 128; t++) {
        const int cur = t & 1;
        const int kt = t * 128;
        cp_wait0();
        __syncthreads();
        if (t + 1 < Sc / 128) { kload(cur ^ 1, kt + 128); cp_commit(); }

        __half* KH = Kst + cur * QB;

        float s[2][4][4] = {};
        #pragma unroll
        for (int kk = 0; kk < 64; kk += 16) {
            unsigned ah[2][4];
            #pragma unroll
            for (int mt = 0; mt < 2; mt++) {
                int row = wm + mt*16 + (g & 1)*8 + r7;
                int col = kk + (g >> 1)*8;
                ldsm4(sptr(Qh + row*SQa + col), ah[mt]);
            }
            #pragma unroll
            for (int np = 0; np < 2; np++) {
                int row = wn + np*16 + (g >> 1)*8 + r7;
                int col = kk + (g & 1)*8;
                unsigned bh[4];
                ldsm4(sptr(KH + row*SQa + col), bh);
                mma_f16(s[0][np*2],   ah[0], bh[0], bh[1]);
                mma_f16(s[0][np*2+1], ah[0], bh[2], bh[3]);
                mma_f16(s[1][np*2],   ah[1], bh[0], bh[1]);
                mma_f16(s[1][np*2+1], ah[1], bh[2], bh[3]);
            }
        }

        #pragma unroll
        for (int mt = 0; mt < 2; mt++) {
            int row0 = wm + mt*16 + (lane >> 2);
            #pragma unroll
            for (int nt = 0; nt < 4; nt++) {
                int col = wn + nt*8 + (lane & 3)*2;
                float e0 = __expf(s[mt][nt][0] * 0.125f) * invr[mt][0];
                float e1 = __expf(s[mt][nt][1] * 0.125f) * invr[mt][0];
                float e2 = __expf(s[mt][nt][2] * 0.125f) * invr[mt][1];
                float e3 = __expf(s[mt][nt][3] * 0.125f) * invr[mt][1];
                *(float2*)(arow + (size_t)row0 * Sc + kt + col)     = make_float2(e0, e1);
                *(float2*)(arow + (size_t)(row0+8) * Sc + kt + col) = make_float2(e2, e3);
            }
        }
    }
}

// ---------------------------------------------------------------------------
// Launcher
// ---------------------------------------------------------------------------
extern "C" void kernel_launch(void* const* d_in, const int* in_sizes, int n_in,
                              void* d_out, int out_size)
{
    const float* x  = (const float*)d_in[0];
    const float* wq = (const float*)d_in[1];
    const float* wk = (const float*)d_in[2];
    const float* wv = (const float*)d_in[3];
    const float* wo = (const float*)d_in[4];
    const float* fc = (const float*)d_in[5];
    const float* fs = (const float*)d_in[6];

    float* out  = (float*)d_out;
    float* attn = out + (size_t)Bc * Sc * DIMc;

    __half* buf;
    cudaGetSymbolAddress((void**)&buf, g_buf);
    const size_t WM = (size_t)DIMc * DIMc;
    __half* X = buf;
    __half* W = buf + 1ull*CHUNK;    // 4 matrices, contiguous
    __half* Q = buf + 2ull*CHUNK;
    __half* K = buf + 3ull*CHUNK;
    __half* V = buf + 4ull*CHUNK;
    __half* C = buf + 5ull*CHUNK;

    const int projSmem = 2 * 2 * PBUF * 2;                  // 40,960 B
    cudaFuncSetAttribute(proj_mma<0>, cudaFuncAttributeMaxDynamicSharedMemorySize, projSmem);
    cudaFuncSetAttribute(proj_mma<1>, cudaFuncAttributeMaxDynamicSharedMemorySize, projSmem);
    cudaFuncSetAttribute(proj_mma<2>, cudaFuncAttributeMaxDynamicSharedMemorySize, projSmem);
    const int attnSmem = (4 * QB + EB) * 2 + 128 * 4;       // 109,056 B
    cudaFuncSetAttribute(attn_mma, cudaFuncAttributeMaxDynamicSharedMemorySize, attnSmem);

    int nCvt = CHUNK / 4 + DIMc * DIMc;   // x float4s + 4 weights float4s
    cvt_all<<<(nCvt + 255) / 256, 256>>>(x, wq, wk, wv, wo, X, W);

    dim3 pgrid(DIMc / 128, TTOT / 128);   // (8, 32)
    proj_mma<2><<<pgrid, 256, projSmem>>>(X, W + 0*WM, nullptr, Q, fc, fs);
    proj_mma<2><<<pgrid, 256, projSmem>>>(X, W + 1*WM, nullptr, K, fc, fs);
    proj_mma<1><<<pgrid, 256, projSmem>>>(X, W + 2*WM, nullptr, V, nullptr, nullptr);

    attn_mma<<<dim3(Sc/128, NHc, Bc), 512, attnSmem>>>(attn, Q, K, V, C);

    proj_mma<0><<<pgrid, 256, projSmem>>>(C, W + 3*WM, out, nullptr, nullptr, nullptr);
}

// round 8
// speedup vs baseline: 2.6538x; 1.1536x over previous
#include <cuda_runtime.h>
#include <cuda_fp16.h>
#include <cstdint>

#define Bc   2
#define Sc   2048
#define DIMc 1024
#define NHc  16
#define HDc  64
#define TTOT (Bc*Sc)
#define CHUNK (TTOT*DIMc)          // 4,194,304 elements

// Scratch arena (fp16), CHUNK units: 0 X | 1 W(4 mats) | 2 Q | 3 K | 4 V | 5 C
__device__ __half g_buf[6ull * CHUNK];

// ---------------------------------------------------------------------------
// helpers
// ---------------------------------------------------------------------------
__device__ __forceinline__ unsigned sptr(const void* p) {
    return (unsigned)__cvta_generic_to_shared(p);
}
__device__ __forceinline__ void cpa16(unsigned d, const void* s) {
    asm volatile("cp.async.cg.shared.global [%0], [%1], 16;" :: "r"(d), "l"(s));
}
__device__ __forceinline__ void cp_commit() { asm volatile("cp.async.commit_group;"); }
__device__ __forceinline__ void cp_wait0()  { asm volatile("cp.async.wait_group 0;"); }
__device__ __forceinline__ void cp_wait1()  { asm volatile("cp.async.wait_group 1;"); }

__device__ __forceinline__ void ldsm4(unsigned a, unsigned* r) {
    asm volatile("ldmatrix.sync.aligned.m8n8.x4.shared.b16 {%0,%1,%2,%3},[%4];"
        : "=r"(r[0]), "=r"(r[1]), "=r"(r[2]), "=r"(r[3]) : "r"(a));
}
__device__ __forceinline__ void ldsm4t(unsigned a, unsigned* r) {
    asm volatile("ldmatrix.sync.aligned.m8n8.x4.trans.shared.b16 {%0,%1,%2,%3},[%4];"
        : "=r"(r[0]), "=r"(r[1]), "=r"(r[2]), "=r"(r[3]) : "r"(a));
}
__device__ __forceinline__ void mma_f16(float* c, const unsigned* a, unsigned b0, unsigned b1) {
    asm volatile(
        "mma.sync.aligned.m16n8k16.row.col.f32.f16.f16.f32 "
        "{%0,%1,%2,%3},{%4,%5,%6,%7},{%8,%9},{%0,%1,%2,%3};"
        : "+f"(c[0]), "+f"(c[1]), "+f"(c[2]), "+f"(c[3])
        : "r"(a[0]), "r"(a[1]), "r"(a[2]), "r"(a[3]), "r"(b0), "r"(b1));
}
__device__ __forceinline__ unsigned packh2(float v0, float v1) {
    unsigned r;
    asm("cvt.rn.f16x2.f32 %0, %1, %2;" : "=r"(r) : "f"(v1), "f"(v0));
    return r;
}

// ---------------------------------------------------------------------------
// One-time convert: x + 4 weight matrices -> fp16
// ---------------------------------------------------------------------------
__global__ void cvt_all(const float* __restrict__ x,
                        const float* __restrict__ wq, const float* __restrict__ wk,
                        const float* __restrict__ wv, const float* __restrict__ wo,
                        __half* __restrict__ X, __half* __restrict__ W)
{
    int i = blockIdx.x * blockDim.x + threadIdx.x;
    const int NX = CHUNK / 4;
    const int NW = (DIMc * DIMc) / 4;
    const float* src; __half* dst; int idx;
    if (i < NX) { src = x; dst = X; idx = i; }
    else {
        int j = i - NX;
        if (j >= 4 * NW) return;
        int m = j >> 18; idx = j & (NW - 1);
        src = (m == 0) ? wq : (m == 1) ? wk : (m == 2) ? wv : wo;
        dst = W + (size_t)m * DIMc * DIMc;
    }
    float4 v = reinterpret_cast<const float4*>(src)[idx];
    reinterpret_cast<uint2*>(dst)[idx] = make_uint2(packh2(v.x, v.y), packh2(v.z, v.w));
}

// ---------------------------------------------------------------------------
// Projection GEMM (fp16): BM=BN=128, BK=64, 3-stage cp.async, 256 thr.
// MODE 0: fp32 out; MODE 1: fp16 out; MODE 2: rope + fp16 out.
// ---------------------------------------------------------------------------
#define SPp   72            // smem row stride (halfs): 144B, LDSM conflict-free
#define PBUFp (128*SPp)     // 9216 halfs per matrix buffer

template<int MODE>
__global__ __launch_bounds__(256, 2) void proj_mma(
    const __half* __restrict__ A_g, const __half* __restrict__ W_g,
    float* __restrict__ OutF, __half* __restrict__ O_g,
    const float* __restrict__ fc, const float* __restrict__ fs)
{
    extern __shared__ __align__(16) __half ps[];   // 3 stages x 2 bufs x PBUFp

    const int tid = threadIdx.x;
    const int warp = tid >> 5, lane = tid & 31;
    const int g = lane >> 3, r7 = lane & 7;
    const int mBase = blockIdx.y * 128, nBase = blockIdx.x * 128;
    const int wm = (warp & 3) * 32, wn = (warp >> 2) * 64;

    float c[2][8][4];
    #pragma unroll
    for (int i = 0; i < 2; i++)
        #pragma unroll
        for (int j = 0; j < 8; j++)
            #pragma unroll
            for (int k = 0; k < 4; k++) c[i][j][k] = 0.f;

    auto pload = [&](int slot, int t) {
        __half* base = ps + slot * 2 * PBUFp;
        int k0 = t * 64;
        #pragma unroll
        for (int i = 0; i < 4; i++) {
            int ch = tid + 256 * i;            // 1024 chunks: 128 rows x 8
            int r = ch >> 3, c8 = (ch & 7) * 8;
            cpa16(sptr(&base[r*SPp + c8]), &A_g[(size_t)(mBase + r) * DIMc + k0 + c8]);
            cpa16(sptr(&base[PBUFp + r*SPp + c8]), &W_g[(size_t)(nBase + r) * DIMc + k0 + c8]);
        }
    };

    pload(0, 0); cp_commit();
    pload(1, 1); cp_commit();

    for (int t = 0; t < 16; t++) {
        int cur = t % 3;
        if (t < 15) cp_wait1(); else cp_wait0();
        __syncthreads();
        if (t + 2 <= 15) { pload((t + 2) % 3, t + 2); cp_commit(); }

        __half* Ah = ps + cur * 2 * PBUFp;
        __half* Bh = Ah + PBUFp;

        #pragma unroll
        for (int kk = 0; kk < 64; kk += 16) {
            unsigned ah[2][4];
            #pragma unroll
            for (int mt = 0; mt < 2; mt++) {
                int row = wm + mt*16 + (g & 1)*8 + r7;
                int col = kk + (g >> 1)*8;
                ldsm4(sptr(&Ah[row*SPp + col]), ah[mt]);
            }
            #pragma unroll
            for (int np = 0; np < 4; np++) {
                int row = wn + np*16 + (g >> 1)*8 + r7;
                int col = kk + (g & 1)*8;
                unsigned bh[4];
                ldsm4(sptr(&Bh[row*SPp + col]), bh);
                mma_f16(c[0][np*2],   ah[0], bh[0], bh[1]);
                mma_f16(c[0][np*2+1], ah[0], bh[2], bh[3]);
                mma_f16(c[1][np*2],   ah[1], bh[0], bh[1]);
                mma_f16(c[1][np*2+1], ah[1], bh[2], bh[3]);
            }
        }
    }

    #pragma unroll
    for (int mt = 0; mt < 2; mt++) {
        int row = mBase + wm + mt*16 + (lane >> 2);
        #pragma unroll
        for (int nt = 0; nt < 8; nt++) {
            int col = nBase + wn + nt*8 + (lane & 3)*2;
            float v0 = c[mt][nt][0], v1 = c[mt][nt][1];
            float v2 = c[mt][nt][2], v3 = c[mt][nt][3];
            if (MODE == 2) {
                int i = (col & 63) >> 1;
                int s0 = row & (Sc-1), s1 = (row + 8) & (Sc-1);
                float c0 = fc[s0*32 + i], sn0 = fs[s0*32 + i];
                float c1 = fc[s1*32 + i], sn1 = fs[s1*32 + i];
                float a0 = v0, b0 = v1, a1 = v2, b1 = v3;
                v0 = a0*c0 - b0*sn0; v1 = a0*sn0 + b0*c0;
                v2 = a1*c1 - b1*sn1; v3 = a1*sn1 + b1*c1;
            }
            if (MODE == 0) {
                *(float2*)(OutF + (size_t)row * DIMc + col)     = make_float2(v0, v1);
                *(float2*)(OutF + (size_t)(row+8) * DIMc + col) = make_float2(v2, v3);
            } else {
                *(unsigned*)&O_g[(size_t)row * DIMc + col]     = packh2(v0, v1);
                *(unsigned*)&O_g[(size_t)(row+8) * DIMc + col] = packh2(v2, v3);
            }
        }
    }
}

// ---------------------------------------------------------------------------
// Attention (fp16): 64-row q-blocks, 256 threads, 2 CTAs/SM.
// Pass 1: scores->exp->rowsum+PV. Pass 2: recompute, write normalized.
// ---------------------------------------------------------------------------
#define SQa 72
#define SEa 136
#define QB64 (64*SQa)     // 4608 halfs (Q tile)
#define KB   (128*SQa)    // 9216 halfs (K/V tiles)
#define EB64 (64*SEa)     // 8704 halfs (E tile)

__global__ __launch_bounds__(256, 2) void attn_mma(
    float* __restrict__ attn,
    const __half* __restrict__ Q_g, const __half* __restrict__ K_g,
    const __half* __restrict__ V_g, __half* __restrict__ C_g)
{
    extern __shared__ __align__(16) __half sm[];
    __half* Qh = sm;                 // QB64
    __half* Kst = Qh + QB64;         // 2 stages x KB
    __half* Vh = Kst + 2*KB;         // KB
    __half* Eh = Vh + KB;            // EB64
    float* rowsum = (float*)(Eh + EB64);   // 64 floats

    const int tid = threadIdx.x;
    const int warp = tid >> 5, lane = tid & 31;
    const int g = lane >> 3, r7 = lane & 7;
    const int qBase = blockIdx.x * 64;
    const int h = blockIdx.y, b = blockIdx.z;

    const size_t qOff = (size_t)(b * Sc + qBase) * DIMc + h * HDc;
    const size_t kvOff = (size_t)b * Sc * DIMc + h * HDc;
    float* arow = attn + ((size_t)(b * NHc + h) * Sc + qBase) * Sc;

    if (tid < 64) rowsum[tid] = 0.f;

    auto kload = [&](int s, int kt) {
        __half* KH = Kst + s * KB;
        #pragma unroll
        for (int i = 0; i < 4; i++) {
            int ch = tid + 256 * i;           // 1024 chunks: 128 rows x 8
            int r = ch >> 3, c8 = (ch & 7) * 8;
            cpa16(sptr(&KH[r*SQa + c8]), &K_g[kvOff + (size_t)(kt + r) * DIMc + c8]);
        }
    };
    auto vload = [&](int kt) {
        #pragma unroll
        for (int i = 0; i < 4; i++) {
            int ch = tid + 256 * i;
            int r = ch >> 3, c8 = (ch & 7) * 8;
            cpa16(sptr(&Vh[r*SQa + c8]), &V_g[kvOff + (size_t)(kt + r) * DIMc + c8]);
        }
    };

    // prologue: Q (64 rows) + K_0
    #pragma unroll
    for (int i = 0; i < 2; i++) {
        int ch = tid + 256 * i;               // 512 chunks: 64 rows x 8
        int r = ch >> 3, c8 = (ch & 7) * 8;
        cpa16(sptr(&Qh[r*SQa + c8]), &Q_g[qOff + (size_t)r * DIMc + c8]);
    }
    kload(0, 0);
    cp_commit();

    // warp grid: scores 2(m:32) x 4(n:32); PV 2(m:32) x 4(d:16)
    const int wmg = (warp & 1) * 32;
    const int wng = (warp >> 1) * 32;
    const int wdg = (warp >> 1) * 16;

    float ctx[2][2][4] = {};
    float rs[4] = {0.f, 0.f, 0.f, 0.f};

    // ---------------- pass 1 ----------------
    for (int t = 0; t < Sc / 128; t++) {
        const int cur = t & 1;
        const int kt = t * 128;
        cp_wait0();
        __syncthreads();                 // K_t (and Q) visible; prev PV done
        vload(kt); cp_commit();          // group: V_t
        const bool pre = (t + 1 < Sc / 128);
        if (pre) { kload(cur ^ 1, kt + 128); cp_commit(); }   // group: K_{t+1}

        __half* KH = Kst + cur * KB;

        float s[2][4][4] = {};
        #pragma unroll
        for (int kk = 0; kk < 64; kk += 16) {
            unsigned ah[2][4];
            #pragma unroll
            for (int mt = 0; mt < 2; mt++) {
                int row = wmg + mt*16 + (g & 1)*8 + r7;
                int col = kk + (g >> 1)*8;
                ldsm4(sptr(Qh + row*SQa + col), ah[mt]);
            }
            #pragma unroll
            for (int np = 0; np < 2; np++) {
                int row = wng + np*16 + (g >> 1)*8 + r7;
                int col = kk + (g & 1)*8;
                unsigned bh[4];
                ldsm4(sptr(KH + row*SQa + col), bh);
                mma_f16(s[0][np*2],   ah[0], bh[0], bh[1]);
                mma_f16(s[0][np*2+1], ah[0], bh[2], bh[3]);
                mma_f16(s[1][np*2],   ah[1], bh[0], bh[1]);
                mma_f16(s[1][np*2+1], ah[1], bh[2], bh[3]);
            }
        }

        if (pre) cp_wait1(); else cp_wait0();   // V_t arrived
        __syncthreads();                        // V visible; E free

        #pragma unroll
        for (int mt = 0; mt < 2; mt++) {
            int row0 = wmg + mt*16 + (lane >> 2);
            #pragma unroll
            for (int nt = 0; nt < 4; nt++) {
                int col = wng + nt*8 + (lane & 3)*2;
                float e0 = __expf(s[mt][nt][0] * 0.125f);
                float e1 = __expf(s[mt][nt][1] * 0.125f);
                float e2 = __expf(s[mt][nt][2] * 0.125f);
                float e3 = __expf(s[mt][nt][3] * 0.125f);
                rs[mt*2+0] += e0 + e1;
                rs[mt*2+1] += e2 + e3;
                *(unsigned*)(Eh + row0*SEa + col)     = packh2(e0, e1);
                *(unsigned*)(Eh + (row0+8)*SEa + col) = packh2(e2, e3);
            }
        }
        __syncthreads();   // E visible

        #pragma unroll
        for (int kk = 0; kk < 128; kk += 16) {
            unsigned ah[2][4];
            #pragma unroll
            for (int mt = 0; mt < 2; mt++) {
                int row = wmg + mt*16 + (g & 1)*8 + r7;
                int col = kk + (g >> 1)*8;
                ldsm4(sptr(Eh + row*SEa + col), ah[mt]);
            }
            int vrow = kk + (g & 1)*8 + r7;
            int vcol = wdg + (g >> 1)*8;
            unsigned bh[4];
            ldsm4t(sptr(Vh + vrow*SQa + vcol), bh);
            mma_f16(ctx[0][0], ah[0], bh[0], bh[1]);
            mma_f16(ctx[0][1], ah[0], bh[2], bh[3]);
            mma_f16(ctx[1][0], ah[1], bh[0], bh[1]);
            mma_f16(ctx[1][1], ah[1], bh[2], bh[3]);
        }
    }

    // rowsum -> inverse
    #pragma unroll
    for (int mt = 0; mt < 2; mt++) {
        int row0 = wmg + mt*16 + (lane >> 2);
        atomicAdd(&rowsum[row0],     rs[mt*2+0]);
        atomicAdd(&rowsum[row0 + 8], rs[mt*2+1]);
    }
    __syncthreads();
    if (tid < 64) rowsum[tid] = 1.0f / rowsum[tid];
    __syncthreads();

    // ctx epilogue: normalize + fp16 store
    #pragma unroll
    for (int mt = 0; mt < 2; mt++) {
        int row0 = wmg + mt*16 + (lane >> 2);
        float iv0 = rowsum[row0], iv1 = rowsum[row0 + 8];
        #pragma unroll
        for (int nt = 0; nt < 2; nt++) {
            int col = wdg + nt*8 + (lane & 3)*2;
            size_t o0 = qOff + (size_t)row0 * DIMc + col;
            size_t o1 = qOff + (size_t)(row0+8) * DIMc + col;
            *(unsigned*)&C_g[o0] = packh2(ctx[mt][nt][0] * iv0, ctx[mt][nt][1] * iv0);
            *(unsigned*)&C_g[o1] = packh2(ctx[mt][nt][2] * iv1, ctx[mt][nt][3] * iv1);
        }
    }

    float invr[2][2];
    #pragma unroll
    for (int mt = 0; mt < 2; mt++) {
        invr[mt][0] = rowsum[wmg + mt*16 + (lane >> 2)];
        invr[mt][1] = rowsum[wmg + mt*16 + 8 + (lane >> 2)];
    }
    __syncthreads();

    // ---------------- pass 2: recompute scores, write normalized ----------------
    kload(0, 0); cp_commit();
    for (int t = 0; t < Sc / 128; t++) {
        const int cur = t & 1;
        const int kt = t * 128;
        cp_wait0();
        __syncthreads();
        if (t + 1 < Sc / 128) { kload(cur ^ 1, kt + 128); cp_commit(); }

        __half* KH = Kst + cur * KB;

        float s[2][4][4] = {};
        #pragma unroll
        for (int kk = 0; kk < 64; kk += 16) {
            unsigned ah[2][4];
            #pragma unroll
            for (int mt = 0; mt < 2; mt++) {
                int row = wmg + mt*16 + (g & 1)*8 + r7;
                int col = kk + (g >> 1)*8;
                ldsm4(sptr(Qh + row*SQa + col), ah[mt]);
            }
            #pragma unroll
            for (int np = 0; np < 2; np++) {
                int row = wng + np*16 + (g >> 1)*8 + r7;
                int col = kk + (g & 1)*8;
                unsigned bh[4];
                ldsm4(sptr(KH + row*SQa + col), bh);
                mma_f16(s[0][np*2],   ah[0], bh[0], bh[1]);
                mma_f16(s[0][np*2+1], ah[0], bh[2], bh[3]);
                mma_f16(s[1][np*2],   ah[1], bh[0], bh[1]);
                mma_f16(s[1][np*2+1], ah[1], bh[2], bh[3]);
            }
        }

        #pragma unroll
        for (int mt = 0; mt < 2; mt++) {
            int row0 = wmg + mt*16 + (lane >> 2);
            #pragma unroll
            for (int nt = 0; nt < 4; nt++) {
                int col = wng + nt*8 + (lane & 3)*2;
                float e0 = __expf(s[mt][nt][0] * 0.125f) * invr[mt][0];
                float e1 = __expf(s[mt][nt][1] * 0.125f) * invr[mt][0];
                float e2 = __expf(s[mt][nt][2] * 0.125f) * invr[mt][1];
                float e3 = __expf(s[mt][nt][3] * 0.125f) * invr[mt][1];
                *(float2*)(arow + (size_t)row0 * Sc + kt + col)     = make_float2(e0, e1);
                *(float2*)(arow + (size_t)(row0+8) * Sc + kt + col) = make_float2(e2, e3);
            }
        }
    }
}

// ---------------------------------------------------------------------------
// Launcher
// ---------------------------------------------------------------------------
extern "C" void kernel_launch(void* const* d_in, const int* in_sizes, int n_in,
                              void* d_out, int out_size)
{
    const float* x  = (const float*)d_in[0];
    const float* wq = (const float*)d_in[1];
    const float* wk = (const float*)d_in[2];
    const float* wv = (const float*)d_in[3];
    const float* wo = (const float*)d_in[4];
    const float* fc = (const float*)d_in[5];
    const float* fs = (const float*)d_in[6];

    float* out  = (float*)d_out;
    float* attn = out + (size_t)Bc * Sc * DIMc;

    __half* buf;
    cudaGetSymbolAddress((void**)&buf, g_buf);
    const size_t WM = (size_t)DIMc * DIMc;
    __half* X = buf;
    __half* W = buf + 1ull*CHUNK;
    __half* Q = buf + 2ull*CHUNK;
    __half* K = buf + 3ull*CHUNK;
    __half* V = buf + 4ull*CHUNK;
    __half* C = buf + 5ull*CHUNK;

    const int projSmem = 3 * 2 * PBUFp * 2;                       // 110,592 B
    cudaFuncSetAttribute(proj_mma<0>, cudaFuncAttributeMaxDynamicSharedMemorySize, projSmem);
    cudaFuncSetAttribute(proj_mma<1>, cudaFuncAttributeMaxDynamicSharedMemorySize, projSmem);
    cudaFuncSetAttribute(proj_mma<2>, cudaFuncAttributeMaxDynamicSharedMemorySize, projSmem);
    const int attnSmem = (QB64 + 2*KB + KB + EB64) * 2 + 64 * 4;  // 82,176 B
    cudaFuncSetAttribute(attn_mma, cudaFuncAttributeMaxDynamicSharedMemorySize, attnSmem);

    int nCvt = CHUNK / 4 + DIMc * DIMc;
    cvt_all<<<(nCvt + 255) / 256, 256>>>(x, wq, wk, wv, wo, X, W);

    dim3 pgrid(DIMc / 128, TTOT / 128);   // (8, 32)
    proj_mma<2><<<pgrid, 256, projSmem>>>(X, W + 0*WM, nullptr, Q, fc, fs);
    proj_mma<2><<<pgrid, 256, projSmem>>>(X, W + 1*WM, nullptr, K, fc, fs);
    proj_mma<1><<<pgrid, 256, projSmem>>>(X, W + 2*WM, nullptr, V, nullptr, nullptr);

    attn_mma<<<dim3(Sc/64, NHc, Bc), 256, attnSmem>>>(attn, Q, K, V, C);

    proj_mma<0><<<pgrid, 256, projSmem>>>(C, W + 3*WM, out, nullptr, nullptr, nullptr);
}